// round 1
// baseline (speedup 1.0000x reference)
#include <cuda_runtime.h>

#define RES    32
#define BATCH  2
#define LTOK   (RES*RES*RES)     // 32768
#define CDIM   256
#define HEADS  8
#define HDV    32                // head dim
#define SWIN   256               // tokens per window (32 x 8)
#define WSP    8
#define SCALE  0.17677669529663687f   // 32^-0.5

#define KSTRIDE 32
#define VSTRIDE 36
#define SMEM_FLOATS (SWIN*KSTRIDE + SWIN*VSTRIDE + 9*HDV + HDV)
#define SMEM_BYTES  (SMEM_FLOATS * 4)

typedef unsigned long long ull;

__device__ __forceinline__ ull pack2(float lo, float hi) {
    ull r;
    asm("mov.b64 %0, {%1, %2};" : "=l"(r)
        : "r"(__float_as_uint(lo)), "r"(__float_as_uint(hi)));
    return r;
}
__device__ __forceinline__ void unpack2(ull v, float& lo, float& hi) {
    unsigned a, b;
    asm("mov.b64 {%0, %1}, %2;" : "=r"(a), "=r"(b) : "l"(v));
    lo = __uint_as_float(a);
    hi = __uint_as_float(b);
}
__device__ __forceinline__ ull ffma2(ull a, ull b, ull c) {
    ull d;
    asm("fma.rn.f32x2 %0, %1, %2, %3;" : "=l"(d) : "l"(a), "l"(b), "l"(c));
    return d;
}
__device__ __forceinline__ ull fmul2(ull a, ull b) {
    ull d;
    asm("mul.rn.f32x2 %0, %1, %2;" : "=l"(d) : "l"(a), "l"(b));
    return d;
}

__global__ void __launch_bounds__(256, 2)
lepe_attn_kernel(const float* __restrict__ qkv,
                 const float* __restrict__ conv_w,
                 const float* __restrict__ conv_b,
                 float* __restrict__ out)
{
    extern __shared__ float smem[];
    float* Ksm = smem;                          // [256][32]
    float* Vsm = Ksm + SWIN * KSTRIDE;          // [256][36]
    float* Wsm = Vsm + SWIN * VSTRIDE;          // [32][9]  conv weights for this head
    float* Bsm = Wsm + 9 * HDV;                 // [32]     conv bias for this head

    const int tid  = threadIdx.x;
    const int head = blockIdx.x & 7;
    const int wi   = blockIdx.x >> 3;
    const int b    = wi >> 7;                   // wi = (b*32 + d)*4 + iw
    const int dsl  = (wi >> 2) & 31;
    const int iw   = wi & 3;
    const int h    = tid >> 3;
    const int w    = tid & 7;
    const int l    = dsl * 1024 + h * 32 + iw * 8 + w;

    const size_t base = ((size_t)b * LTOK + l) * CDIM + head * HDV;
    const float* qp = qkv + base;
    const float* kp = qkv + (size_t)BATCH * LTOK * CDIM + base;
    const float* vp = qkv + 2 * (size_t)BATCH * LTOK * CDIM + base;

    // ---- stage K, V into smem (each thread owns its token's 32 channels),
    //      load own Q row into registers (pre-scaled) ----
    float q[HDV];
#pragma unroll
    for (int i = 0; i < 8; i++) {
        float4 kk = *(const float4*)(kp + i * 4);
        *(float4*)(Ksm + tid * KSTRIDE + i * 4) = kk;
        float4 vv = *(const float4*)(vp + i * 4);
        *(float4*)(Vsm + tid * VSTRIDE + i * 4) = vv;
        float4 qq = *(const float4*)(qp + i * 4);
        q[i*4+0] = qq.x * SCALE; q[i*4+1] = qq.y * SCALE;
        q[i*4+2] = qq.z * SCALE; q[i*4+3] = qq.w * SCALE;
    }
    // conv weights/bias for this head's 32 channels (contiguous block of 288 floats)
    for (int i = tid; i < 9 * HDV; i += 256) Wsm[i] = conv_w[head * HDV * 9 + i];
    if (tid < HDV) Bsm[tid] = conv_b[head * HDV + tid];
    __syncthreads();

    ull q2[16];
#pragma unroll
    for (int i = 0; i < 16; i++) q2[i] = pack2(q[2*i], q[2*i+1]);

    // ---- flash-style chunked softmax over 256 keys; this thread = query row s=tid ----
    float m = -1e30f, lsum = 0.f;
    ull o2[16];
#pragma unroll
    for (int i = 0; i < 16; i++) o2[i] = 0ull;   // bits of (0.f, 0.f)

    for (int c0 = 0; c0 < SWIN; c0 += 16) {
        float sc[16];
#pragma unroll
        for (int j = 0; j < 16; j++) {
            const float* krow = Ksm + (c0 + j) * KSTRIDE;
            ull acc = 0ull;
#pragma unroll
            for (int dd = 0; dd < HDV; dd += 4) {
                ulonglong2 kk = *(const ulonglong2*)(krow + dd);
                acc = ffma2(q2[dd >> 1],       kk.x, acc);
                acc = ffma2(q2[(dd >> 1) + 1], kk.y, acc);
            }
            float lo, hi; unpack2(acc, lo, hi);
            sc[j] = lo + hi;
        }
        float cm = sc[0];
#pragma unroll
        for (int j = 1; j < 16; j++) cm = fmaxf(cm, sc[j]);
        float mnew = fmaxf(m, cm);
        float corr = __expf(m - mnew);
        lsum *= corr;
        ull corr2 = pack2(corr, corr);
#pragma unroll
        for (int i = 0; i < 16; i++) o2[i] = fmul2(o2[i], corr2);

#pragma unroll
        for (int j = 0; j < 16; j++) {
            float p = __expf(sc[j] - mnew);
            lsum += p;
            ull p2 = pack2(p, p);
            const float* vrow = Vsm + (c0 + j) * VSTRIDE;
#pragma unroll
            for (int dd = 0; dd < HDV; dd += 4) {
                ulonglong2 vv = *(const ulonglong2*)(vrow + dd);
                o2[dd >> 1]       = ffma2(p2, vv.x, o2[dd >> 1]);
                o2[(dd >> 1) + 1] = ffma2(p2, vv.y, o2[(dd >> 1) + 1]);
            }
        }
        m = mnew;
    }

    const float inv = 1.0f / lsum;
    float o[HDV];
#pragma unroll
    for (int i = 0; i < 16; i++) unpack2(o2[i], o[2*i], o[2*i+1]);

    // ---- LePE: depthwise 3x3 conv (SAME, zero-pad) inside the 32x8 window, fused ----
#pragma unroll
    for (int d = 0; d < HDV; d++) {
        float acc = Bsm[d];
#pragma unroll
        for (int kh = 0; kh < 3; kh++) {
            int hh = h + kh - 1;
            if (hh < 0 || hh >= RES) continue;
#pragma unroll
            for (int kw = 0; kw < 3; kw++) {
                int ww = w + kw - 1;
                if (ww < 0 || ww >= WSP) continue;
                acc += Wsm[d * 9 + kh * 3 + kw] * Vsm[(hh * WSP + ww) * VSTRIDE + d];
            }
        }
        o[d] = o[d] * inv + acc;
    }

    float* op = out + base;
#pragma unroll
    for (int i = 0; i < 8; i++) {
        *(float4*)(op + i * 4) =
            make_float4(o[i*4], o[i*4+1], o[i*4+2], o[i*4+3]);
    }
}

extern "C" void kernel_launch(void* const* d_in, const int* in_sizes, int n_in,
                              void* d_out, int out_size)
{
    const float* qkv    = (const float*)d_in[0];
    const float* conv_w = (const float*)d_in[1];
    const float* conv_b = (const float*)d_in[2];
    float* out = (float*)d_out;

    cudaFuncSetAttribute(lepe_attn_kernel,
                         cudaFuncAttributeMaxDynamicSharedMemorySize, SMEM_BYTES);
    const int nblocks = (BATCH * RES * (RES / WSP)) * HEADS;  // 256 windows * 8 heads = 2048
    lepe_attn_kernel<<<nblocks, 256, SMEM_BYTES>>>(qkv, conv_w, conv_b, out);
}

// round 2
// speedup vs baseline: 1.3300x; 1.3300x over previous
#include <cuda_runtime.h>

#define RES    32
#define BATCH  2
#define LTOK   (RES*RES*RES)     // 32768
#define CDIM   256
#define HEADS  8
#define HDV    32                // head dim
#define SWIN   256               // tokens per window (32 x 8)
#define WSP    8
#define SCALE  0.17677669529663687f   // 32^-0.5

#define KSTRIDE 32
#define VSTRIDE 36
#define NTHREADS 128
#define SMEM_FLOATS (SWIN*KSTRIDE + SWIN*VSTRIDE + 9*HDV + HDV)
#define SMEM_BYTES  (SMEM_FLOATS * 4)

typedef unsigned long long ull;

__device__ __forceinline__ ull pack2(float lo, float hi) {
    ull r;
    asm("mov.b64 %0, {%1, %2};" : "=l"(r)
        : "r"(__float_as_uint(lo)), "r"(__float_as_uint(hi)));
    return r;
}
__device__ __forceinline__ void unpack2(ull v, float& lo, float& hi) {
    unsigned a, b;
    asm("mov.b64 {%0, %1}, %2;" : "=r"(a), "=r"(b) : "l"(v));
    lo = __uint_as_float(a);
    hi = __uint_as_float(b);
}
__device__ __forceinline__ ull ffma2(ull a, ull b, ull c) {
    ull d;
    asm("fma.rn.f32x2 %0, %1, %2, %3;" : "=l"(d) : "l"(a), "l"(b), "l"(c));
    return d;
}
__device__ __forceinline__ ull fmul2(ull a, ull b) {
    ull d;
    asm("mul.rn.f32x2 %0, %1, %2;" : "=l"(d) : "l"(a), "l"(b));
    return d;
}

__global__ void __launch_bounds__(NTHREADS, 2)
lepe_attn_kernel(const float* __restrict__ qkv,
                 const float* __restrict__ conv_w,
                 const float* __restrict__ conv_b,
                 float* __restrict__ out)
{
    extern __shared__ float smem[];
    float* Ksm = smem;                          // [256][32]
    float* Vsm = Ksm + SWIN * KSTRIDE;          // [256][36]
    float* Wsm = Vsm + SWIN * VSTRIDE;          // [32][9]
    float* Bsm = Wsm + 9 * HDV;                 // [32]

    const int tid  = threadIdx.x;
    const int head = blockIdx.x & 7;
    const int wi   = blockIdx.x >> 3;
    const int b    = wi >> 7;                   // wi = (b*32 + d)*4 + iw
    const int dsl  = (wi >> 2) & 31;
    const int iw   = wi & 3;

    size_t base[2];
    ull q2[2][16];

    // ---- stage K, V (2 tokens per thread) + load both Q rows (pre-scaled) ----
#pragma unroll
    for (int qi = 0; qi < 2; qi++) {
        const int s = tid + qi * NTHREADS;
        const int h = s >> 3;
        const int w = s & 7;
        const int l = dsl * 1024 + h * 32 + iw * 8 + w;
        base[qi] = ((size_t)b * LTOK + l) * CDIM + head * HDV;
        const float* qp = qkv + base[qi];
        const float* kp = qkv + (size_t)BATCH * LTOK * CDIM + base[qi];
        const float* vp = qkv + 2 * (size_t)BATCH * LTOK * CDIM + base[qi];
#pragma unroll
        for (int i = 0; i < 8; i++) {
            float4 kk = *(const float4*)(kp + i * 4);
            *(float4*)(Ksm + s * KSTRIDE + i * 4) = kk;
            float4 vv = *(const float4*)(vp + i * 4);
            *(float4*)(Vsm + s * VSTRIDE + i * 4) = vv;
            float4 qq = *(const float4*)(qp + i * 4);
            q2[qi][i*2]   = pack2(qq.x * SCALE, qq.y * SCALE);
            q2[qi][i*2+1] = pack2(qq.z * SCALE, qq.w * SCALE);
        }
    }
    for (int i = tid; i < 9 * HDV; i += NTHREADS) Wsm[i] = conv_w[head * HDV * 9 + i];
    if (tid < HDV) Bsm[tid] = conv_b[head * HDV + tid];
    __syncthreads();

    // ---- flash-style chunked softmax over 256 keys, 2 query rows per thread ----
    float m[2]    = {-1e30f, -1e30f};
    float lsum[2] = {0.f, 0.f};
    ull o2[2][16];
#pragma unroll
    for (int i = 0; i < 16; i++) { o2[0][i] = 0ull; o2[1][i] = 0ull; }

    for (int c0 = 0; c0 < SWIN; c0 += 16) {
        float sc[2][16];
#pragma unroll
        for (int j = 0; j < 16; j++) {
            const float* krow = Ksm + (c0 + j) * KSTRIDE;
            ull a0 = 0ull, a1 = 0ull;
#pragma unroll
            for (int dd = 0; dd < HDV; dd += 4) {
                ulonglong2 kk = *(const ulonglong2*)(krow + dd);
                a0 = ffma2(q2[0][dd >> 1],       kk.x, a0);
                a0 = ffma2(q2[0][(dd >> 1) + 1], kk.y, a0);
                a1 = ffma2(q2[1][dd >> 1],       kk.x, a1);
                a1 = ffma2(q2[1][(dd >> 1) + 1], kk.y, a1);
            }
            float lo, hi;
            unpack2(a0, lo, hi); sc[0][j] = lo + hi;
            unpack2(a1, lo, hi); sc[1][j] = lo + hi;
        }
        // softmax bookkeeping per query; sc[qi][j] becomes p
#pragma unroll
        for (int qi = 0; qi < 2; qi++) {
            float cm = sc[qi][0];
#pragma unroll
            for (int j = 1; j < 16; j++) cm = fmaxf(cm, sc[qi][j]);
            float mnew = fmaxf(m[qi], cm);
            float corr = __expf(m[qi] - mnew);
            m[qi] = mnew;
            float ls = lsum[qi] * corr;
            ull corr2 = pack2(corr, corr);
#pragma unroll
            for (int i = 0; i < 16; i++) o2[qi][i] = fmul2(o2[qi][i], corr2);
#pragma unroll
            for (int j = 0; j < 16; j++) {
                float p = __expf(sc[qi][j] - mnew);
                ls += p;
                sc[qi][j] = p;
            }
            lsum[qi] = ls;
        }
        // single V pass serves both query rows
#pragma unroll
        for (int j = 0; j < 16; j++) {
            const float* vrow = Vsm + (c0 + j) * VSTRIDE;
            ull p0 = pack2(sc[0][j], sc[0][j]);
            ull p1 = pack2(sc[1][j], sc[1][j]);
#pragma unroll
            for (int dd = 0; dd < HDV; dd += 4) {
                ulonglong2 vv = *(const ulonglong2*)(vrow + dd);
                o2[0][dd >> 1]       = ffma2(p0, vv.x, o2[0][dd >> 1]);
                o2[0][(dd >> 1) + 1] = ffma2(p0, vv.y, o2[0][(dd >> 1) + 1]);
                o2[1][dd >> 1]       = ffma2(p1, vv.x, o2[1][dd >> 1]);
                o2[1][(dd >> 1) + 1] = ffma2(p1, vv.y, o2[1][(dd >> 1) + 1]);
            }
        }
    }

    // ---- epilogue: normalize + fused LePE conv + store, per query row ----
#pragma unroll
    for (int qi = 0; qi < 2; qi++) {
        const int s = tid + qi * NTHREADS;
        const int h = s >> 3;
        const int w = s & 7;
        const float inv = 1.0f / lsum[qi];
        float o[HDV];
#pragma unroll
        for (int i = 0; i < 16; i++) unpack2(o2[qi][i], o[2*i], o[2*i+1]);

#pragma unroll
        for (int d = 0; d < HDV; d++) {
            float acc = Bsm[d];
#pragma unroll
            for (int kh = 0; kh < 3; kh++) {
                int hh = h + kh - 1;
                if (hh < 0 || hh >= RES) continue;
#pragma unroll
                for (int kw = 0; kw < 3; kw++) {
                    int ww = w + kw - 1;
                    if (ww < 0 || ww >= WSP) continue;
                    acc += Wsm[d * 9 + kh * 3 + kw] * Vsm[(hh * WSP + ww) * VSTRIDE + d];
                }
            }
            o[d] = o[d] * inv + acc;
        }

        float* op = out + base[qi];
#pragma unroll
        for (int i = 0; i < 8; i++) {
            *(float4*)(op + i * 4) =
                make_float4(o[i*4], o[i*4+1], o[i*4+2], o[i*4+3]);
        }
    }
}

extern "C" void kernel_launch(void* const* d_in, const int* in_sizes, int n_in,
                              void* d_out, int out_size)
{
    const float* qkv    = (const float*)d_in[0];
    const float* conv_w = (const float*)d_in[1];
    const float* conv_b = (const float*)d_in[2];
    float* out = (float*)d_out;

    cudaFuncSetAttribute(lepe_attn_kernel,
                         cudaFuncAttributeMaxDynamicSharedMemorySize, SMEM_BYTES);
    const int nblocks = (BATCH * RES * (RES / WSP)) * HEADS;  // 2048
    lepe_attn_kernel<<<nblocks, NTHREADS, SMEM_BYTES>>>(qkv, conv_w, conv_b, out);
}

// round 4
// speedup vs baseline: 2.4121x; 1.8136x over previous
#include <cuda_runtime.h>
#include <stdint.h>

#define RES    32
#define BATCH  2
#define LTOK   32768
#define CDIM   256
#define HEADS  8
#define HDV    32
#define SWIN   256
#define SCALEF 0.17677669529663687f

#define NT     256      // threads per block (8 warps)
#define QSTR   36       // Q/K smem row stride (floats): banks 4g+tg, conflict-free
#define VSTR   40       // V smem row stride (floats): banks 8tg+g, conflict-free

// smem layout (float offsets)
#define QS_OFF 0                      // Q tf32 [256][36]  (reused as O staging)
#define KS_OFF (QS_OFF + SWIN*QSTR)   // K tf32 [256][36]
#define VS_OFF (KS_OFF + SWIN*QSTR)   // V fp32 [256][40]
#define W_OFF  (VS_OFF + SWIN*VSTR)   // conv w 288
#define B_OFF  (W_OFF + 9*HDV)        // conv b 32
#define SMEM_FLOATS (B_OFF + HDV)
#define SMEM_BYTES  (SMEM_FLOATS * 4)

__device__ __forceinline__ uint32_t f2tf32(float f) {
    uint32_t r; asm("cvt.rna.tf32.f32 %0, %1;" : "=r"(r) : "f"(f)); return r;
}

__device__ __forceinline__ void mma_tf32(float* d, const uint32_t* a, const uint32_t* b) {
    asm("mma.sync.aligned.m16n8k8.row.col.f32.tf32.tf32.f32 "
        "{%0,%1,%2,%3}, {%4,%5,%6,%7}, {%8,%9}, {%0,%1,%2,%3};"
        : "+f"(d[0]), "+f"(d[1]), "+f"(d[2]), "+f"(d[3])
        : "r"(a[0]), "r"(a[1]), "r"(a[2]), "r"(a[3]), "r"(b[0]), "r"(b[1]));
}

__global__ void __launch_bounds__(NT)
lepe_attn_mma(const float* __restrict__ qkv,
              const float* __restrict__ conv_w,
              const float* __restrict__ conv_b,
              float* __restrict__ out)
{
    extern __shared__ float smem[];
    float* Qsm = smem + QS_OFF;      // later reused as O staging
    float* Ksm = smem + KS_OFF;
    float* Vsm = smem + VS_OFF;
    float* Wsm = smem + W_OFF;
    float* Bsm = smem + B_OFF;

    const int tid  = threadIdx.x;
    const int lane = tid & 31;
    const int warp = tid >> 5;
    const int g    = lane >> 2;      // group id (row within tile)
    const int tg   = lane & 3;       // thread in group

    const int head = blockIdx.x & 7;
    const int wi   = blockIdx.x >> 3;
    const int b    = wi >> 7;
    const int dsl  = (wi >> 2) & 31;
    const int iw   = wi & 3;

    // ---- stage Q (tf32, pre-scaled), K (tf32), V (raw fp32); 1 token/thread ----
    {
        const int s = tid;
        const int l = dsl * 1024 + (s >> 3) * 32 + iw * 8 + (s & 7);
        const size_t base = ((size_t)b * LTOK + l) * CDIM + head * HDV;
        const float* qp = qkv + base;
        const float* kp = qkv + (size_t)BATCH * LTOK * CDIM + base;
        const float* vp = qkv + 2 * (size_t)BATCH * LTOK * CDIM + base;
#pragma unroll
        for (int i = 0; i < 8; i++) {
            float4 qq = *(const float4*)(qp + i * 4);
            *(uint4*)(Qsm + s * QSTR + i * 4) = make_uint4(
                f2tf32(qq.x * SCALEF), f2tf32(qq.y * SCALEF),
                f2tf32(qq.z * SCALEF), f2tf32(qq.w * SCALEF));
            float4 kk = *(const float4*)(kp + i * 4);
            *(uint4*)(Ksm + s * QSTR + i * 4) = make_uint4(
                f2tf32(kk.x), f2tf32(kk.y), f2tf32(kk.z), f2tf32(kk.w));
            *(float4*)(Vsm + s * VSTR + i * 4) = *(const float4*)(vp + i * 4);
        }
        for (int i = tid; i < 9 * HDV; i += NT) Wsm[i] = conv_w[head * HDV * 9 + i];
        if (tid < HDV) Bsm[tid] = conv_b[head * HDV + tid];
    }
    __syncthreads();

    // ---- per-warp Q fragments: 2 m-tiles x 4 k-steps ----
    const int m0 = warp * 32;
    uint32_t qf[2][4][4];
#pragma unroll
    for (int mt = 0; mt < 2; mt++) {
        const int r0 = m0 + mt * 16 + g;
#pragma unroll
        for (int ks = 0; ks < 4; ks++) {
            const int c = ks * 8 + tg;
            qf[mt][ks][0] = __float_as_uint(Qsm[r0 * QSTR + c]);
            qf[mt][ks][1] = __float_as_uint(Qsm[(r0 + 8) * QSTR + c]);
            qf[mt][ks][2] = __float_as_uint(Qsm[r0 * QSTR + c + 4]);
            qf[mt][ks][3] = __float_as_uint(Qsm[(r0 + 8) * QSTR + c + 4]);
        }
    }
    __syncthreads();   // all warps done reading Qsm before it becomes O staging

    float o[2][4][4];
    float rs[2][2];    // row sums: [mt][0]=row g, [mt][1]=row g+8
#pragma unroll
    for (int mt = 0; mt < 2; mt++) {
        rs[mt][0] = 0.f; rs[mt][1] = 0.f;
#pragma unroll
        for (int nt = 0; nt < 4; nt++)
#pragma unroll
            for (int i = 0; i < 4; i++) o[mt][nt][i] = 0.f;
    }

    const unsigned srcA = (lane & 28) | (tg >> 1);
    const bool oddc = (tg & 1);

    // ---- main loop: 8 chunks of 32 keys, fully warp-local ----
    for (int c0 = 0; c0 < SWIN; c0 += 32) {
        float p[2][4][4];
#pragma unroll
        for (int mt = 0; mt < 2; mt++)
#pragma unroll
            for (int nt = 0; nt < 4; nt++)
#pragma unroll
                for (int i = 0; i < 4; i++) p[mt][nt][i] = 0.f;

        // S = Q K^T for this chunk
#pragma unroll
        for (int nt = 0; nt < 4; nt++) {
            const int key = c0 + nt * 8 + g;
#pragma unroll
            for (int ks = 0; ks < 4; ks++) {
                uint32_t kb[2];
                kb[0] = __float_as_uint(Ksm[key * QSTR + ks * 8 + tg]);
                kb[1] = __float_as_uint(Ksm[key * QSTR + ks * 8 + tg + 4]);
                mma_tf32(p[0][nt], qf[0][ks], kb);
                mma_tf32(p[1][nt], qf[1][ks], kb);
            }
        }

        // exp (no max pass) + row-sum partials + tf32 re-encode
#pragma unroll
        for (int mt = 0; mt < 2; mt++)
#pragma unroll
            for (int nt = 0; nt < 4; nt++) {
                float e0 = __expf(p[mt][nt][0]);
                float e1 = __expf(p[mt][nt][1]);
                float e2 = __expf(p[mt][nt][2]);
                float e3 = __expf(p[mt][nt][3]);
                rs[mt][0] += e0 + e1;
                rs[mt][1] += e2 + e3;
                p[mt][nt][0] = __uint_as_float(f2tf32(e0));
                p[mt][nt][1] = __uint_as_float(f2tf32(e1));
                p[mt][nt][2] = __uint_as_float(f2tf32(e2));
                p[mt][nt][3] = __uint_as_float(f2tf32(e3));
            }

        // O += P V  (C-frag -> A-frag via shuffles)
#pragma unroll
        for (int kk = 0; kk < 4; kk++) {
            uint32_t vb[4][2];
            const int krow = c0 + kk * 8 + tg;
#pragma unroll
            for (int nt2 = 0; nt2 < 4; nt2++) {
                vb[nt2][0] = f2tf32(Vsm[krow * VSTR + nt2 * 8 + g]);
                vb[nt2][1] = f2tf32(Vsm[(krow + 4) * VSTR + nt2 * 8 + g]);
            }
#pragma unroll
            for (int mt = 0; mt < 2; mt++) {
                uint32_t a[4];
                {
                    float c0r = p[mt][kk][0], c1r = p[mt][kk][1];
                    float c2r = p[mt][kk][2], c3r = p[mt][kk][3];
                    float e0 = __shfl_sync(0xffffffffu, c0r, srcA);
                    float e1 = __shfl_sync(0xffffffffu, c1r, srcA);
                    a[0] = __float_as_uint(oddc ? e1 : e0);
                    e0 = __shfl_sync(0xffffffffu, c2r, srcA);
                    e1 = __shfl_sync(0xffffffffu, c3r, srcA);
                    a[1] = __float_as_uint(oddc ? e1 : e0);
                    e0 = __shfl_sync(0xffffffffu, c0r, srcA + 2);
                    e1 = __shfl_sync(0xffffffffu, c1r, srcA + 2);
                    a[2] = __float_as_uint(oddc ? e1 : e0);
                    e0 = __shfl_sync(0xffffffffu, c2r, srcA + 2);
                    e1 = __shfl_sync(0xffffffffu, c3r, srcA + 2);
                    a[3] = __float_as_uint(oddc ? e1 : e0);
                }
                mma_tf32(o[mt][0], a, vb[0]);
                mma_tf32(o[mt][1], a, vb[1]);
                mma_tf32(o[mt][2], a, vb[2]);
                mma_tf32(o[mt][3], a, vb[3]);
            }
        }
    }

    // ---- row-sum quad reduction + normalized O -> smem staging ----
#pragma unroll
    for (int mt = 0; mt < 2; mt++) {
#pragma unroll
        for (int r = 0; r < 2; r++) {
            float s = rs[mt][r];
            s += __shfl_xor_sync(0xffffffffu, s, 1);
            s += __shfl_xor_sync(0xffffffffu, s, 2);
            rs[mt][r] = 1.0f / s;
        }
        const int r0 = m0 + mt * 16 + g;
#pragma unroll
        for (int nt = 0; nt < 4; nt++) {
            *(float2*)(Qsm + r0 * QSTR + nt * 8 + 2 * tg) =
                make_float2(o[mt][nt][0] * rs[mt][0], o[mt][nt][1] * rs[mt][0]);
            *(float2*)(Qsm + (r0 + 8) * QSTR + nt * 8 + 2 * tg) =
                make_float2(o[mt][nt][2] * rs[mt][1], o[mt][nt][3] * rs[mt][1]);
        }
    }
    __syncthreads();

    // ---- epilogue: per-token normalize-done O + LePE conv + store ----
    {
        const int s = tid;
        const int h = s >> 3, w = s & 7;
        float ov[32];
#pragma unroll
        for (int i = 0; i < 8; i++) {
            float4 t = *(const float4*)(Qsm + s * QSTR + i * 4);
            ov[i*4] = t.x + Bsm[i*4]; ov[i*4+1] = t.y + Bsm[i*4+1];
            ov[i*4+2] = t.z + Bsm[i*4+2]; ov[i*4+3] = t.w + Bsm[i*4+3];
        }
#pragma unroll
        for (int dh = -1; dh <= 1; dh++) {
            int hh = h + dh;
            if (hh < 0 || hh >= RES) continue;
#pragma unroll
            for (int dw = -1; dw <= 1; dw++) {
                int ww = w + dw;
                if (ww < 0 || ww >= 8) continue;
                const int k = hh * 8 + ww;
                const int t = (dh + 1) * 3 + (dw + 1);
#pragma unroll
                for (int d = 0; d < 32; d++)
                    ov[d] += Wsm[d * 9 + t] * Vsm[k * VSTR + d];
            }
        }
        const int l = dsl * 1024 + h * 32 + iw * 8 + w;
        float* op = out + ((size_t)b * LTOK + l) * CDIM + head * HDV;
#pragma unroll
        for (int i = 0; i < 8; i++)
            *(float4*)(op + i * 4) = make_float4(ov[i*4], ov[i*4+1], ov[i*4+2], ov[i*4+3]);
    }
}

extern "C" void kernel_launch(void* const* d_in, const int* in_sizes, int n_in,
                              void* d_out, int out_size)
{
    const float* qkv    = (const float*)d_in[0];
    const float* conv_w = (const float*)d_in[1];
    const float* conv_b = (const float*)d_in[2];
    float* out = (float*)d_out;

    cudaFuncSetAttribute(lepe_attn_mma,
                         cudaFuncAttributeMaxDynamicSharedMemorySize, SMEM_BYTES);
    lepe_attn_mma<<<2048, NT, SMEM_BYTES>>>(qkv, conv_w, conv_b, out);
}

// round 5
// speedup vs baseline: 2.4266x; 1.0060x over previous
#include <cuda_runtime.h>
#include <stdint.h>

#define RES    32
#define BATCH  2
#define LTOK   32768
#define CDIM   256
#define HEADS  8
#define HDV    32
#define SWIN   256
#define SCALEF 0.17677669529663687f

#define NT     256
#define QSTR   36       // Q/K row stride (floats); 144B = 9*16 (ldmatrix-aligned)
#define VTSTR  260      // V^T row stride (floats); 1040B = 65*16

// smem layout (float offsets)
#define QS_OFF 0                        // Q tf32 [256][36] -> P buffer -> O staging
#define KS_OFF (QS_OFF + SWIN*QSTR)     // K tf32 [256][36]
#define VT_OFF (KS_OFF + SWIN*QSTR)     // V^T tf32 [32][260]
#define W_OFF  (VT_OFF + HDV*VTSTR)     // conv w 288
#define B_OFF  (W_OFF + 9*HDV)          // conv b 32
#define SMEM_FLOATS (B_OFF + HDV)
#define SMEM_BYTES  (SMEM_FLOATS * 4)   // 108,288 B -> 2 blocks/SM

__device__ __forceinline__ uint32_t f2tf32(float f) {
    uint32_t r; asm("cvt.rna.tf32.f32 %0, %1;" : "=r"(r) : "f"(f)); return r;
}
__device__ __forceinline__ uint32_t smem_u32(const void* p) {
    uint32_t a;
    asm("{ .reg .u64 t; cvta.to.shared.u64 t, %1; cvt.u32.u64 %0, t; }" : "=r"(a) : "l"(p));
    return a;
}
__device__ __forceinline__ void ldsm4(uint32_t* r, uint32_t addr) {
    asm volatile("ldmatrix.sync.aligned.m8n8.x4.shared.b16 {%0,%1,%2,%3}, [%4];"
        : "=r"(r[0]), "=r"(r[1]), "=r"(r[2]), "=r"(r[3]) : "r"(addr));
}
__device__ __forceinline__ void sts64(uint32_t addr, uint32_t a, uint32_t b) {
    asm volatile("st.shared.v2.b32 [%0], {%1, %2};" :: "r"(addr), "r"(a), "r"(b) : "memory");
}
__device__ __forceinline__ void mma_tf32(float* d, const uint32_t* a, const uint32_t* b) {
    asm("mma.sync.aligned.m16n8k8.row.col.f32.tf32.tf32.f32 "
        "{%0,%1,%2,%3}, {%4,%5,%6,%7}, {%8,%9}, {%0,%1,%2,%3};"
        : "+f"(d[0]), "+f"(d[1]), "+f"(d[2]), "+f"(d[3])
        : "r"(a[0]), "r"(a[1]), "r"(a[2]), "r"(a[3]), "r"(b[0]), "r"(b[1]));
}

__global__ void __launch_bounds__(NT, 2)
lepe_attn_mma(const float* __restrict__ qkv,
              const float* __restrict__ conv_w,
              const float* __restrict__ conv_b,
              float* __restrict__ out)
{
    extern __shared__ float smem[];
    float* Qsm = smem + QS_OFF;
    float* Wsm = smem + W_OFF;
    float* Bsm = smem + B_OFF;
    const uint32_t sb = smem_u32(smem);

    const int tid  = threadIdx.x;
    const int lane = tid & 31;
    const int warp = tid >> 5;
    const int g    = lane >> 2;
    const int tg   = lane & 3;
    const int m0   = warp * 32;

    const int head = blockIdx.x & 7;
    const int wi   = blockIdx.x >> 3;
    const int b    = wi >> 7;
    const int dsl  = (wi >> 2) & 31;
    const int iw   = wi & 3;

    // ---- stage: Q (tf32, scaled) -> Qsm; K (tf32) -> Ksm; V (tf32) -> V^T ----
    {
        const int s = tid;
        const int l = dsl * 1024 + (s >> 3) * 32 + iw * 8 + (s & 7);
        const size_t base = ((size_t)b * LTOK + l) * CDIM + head * HDV;
        const float* qp = qkv + base;
        const float* kp = qkv + (size_t)BATCH * LTOK * CDIM + base;
        const float* vp = qkv + 2 * (size_t)BATCH * LTOK * CDIM + base;
#pragma unroll
        for (int i = 0; i < 8; i++) {
            float4 qq = *(const float4*)(qp + i * 4);
            *(uint4*)(smem + QS_OFF + s * QSTR + i * 4) = make_uint4(
                f2tf32(qq.x * SCALEF), f2tf32(qq.y * SCALEF),
                f2tf32(qq.z * SCALEF), f2tf32(qq.w * SCALEF));
            float4 kk = *(const float4*)(kp + i * 4);
            *(uint4*)(smem + KS_OFF + s * QSTR + i * 4) = make_uint4(
                f2tf32(kk.x), f2tf32(kk.y), f2tf32(kk.z), f2tf32(kk.w));
            float4 vv = *(const float4*)(vp + i * 4);
            ((uint32_t*)smem)[VT_OFF + (i*4+0) * VTSTR + s] = f2tf32(vv.x);
            ((uint32_t*)smem)[VT_OFF + (i*4+1) * VTSTR + s] = f2tf32(vv.y);
            ((uint32_t*)smem)[VT_OFF + (i*4+2) * VTSTR + s] = f2tf32(vv.z);
            ((uint32_t*)smem)[VT_OFF + (i*4+3) * VTSTR + s] = f2tf32(vv.w);
        }
        for (int i = tid; i < 9 * HDV; i += NT) Wsm[i] = conv_w[head * HDV * 9 + i];
        if (tid < HDV) Bsm[tid] = conv_b[head * HDV + tid];
    }
    __syncthreads();

    // lane-derived ldmatrix base addresses
    const int lane7 = lane & 7;
    const int lb8   = (lane >> 3) & 1;
    const int lb16  = (lane >> 4) & 1;
    // A-pattern (Q frags, P frags): tiles [r0-7,cL][r8-15,cL][r0-7,cH][r8-15,cH]
    const uint32_t a_base = sb + (QS_OFF + (m0 + lane7 + lb8 * 8) * QSTR) * 4 + lb16 * 16;
    // B-pattern K: tiles [keys+0-7,cL][cH][keys+8-15,cL][cH]
    const uint32_t k_base = sb + (KS_OFF + (lane7 + lb16 * 8) * QSTR) * 4 + lb8 * 16;
    // B-pattern V^T: tiles [d0-7,keyL][keyH][d8-15,keyL][keyH]
    const uint32_t v_base = sb + (VT_OFF + (lane7 + lb16 * 8) * VTSTR) * 4 + lb8 * 16;
    // P store address (c0,c1)->row m0+mt*16+g col nt*8+2tg ; (c2,c3)->row+8
    const uint32_t p_st = sb + (QS_OFF + (m0 + g) * QSTR + 2 * tg) * 4;

    // ---- Q fragments: 2 m-tiles x 4 k-steps ----
    uint32_t qf[2][4][4];
#pragma unroll
    for (int mt = 0; mt < 2; mt++)
#pragma unroll
        for (int ks = 0; ks < 4; ks++)
            ldsm4(qf[mt][ks], a_base + mt * (16 * QSTR * 4) + ks * 32);

    float o[2][4][4];
    float rs[2][2];
#pragma unroll
    for (int mt = 0; mt < 2; mt++) {
        rs[mt][0] = 0.f; rs[mt][1] = 0.f;
#pragma unroll
        for (int nt = 0; nt < 4; nt++)
#pragma unroll
            for (int i = 0; i < 4; i++) o[mt][nt][i] = 0.f;
    }
    __syncwarp();

    // ---- main loop: 8 chunks of 32 keys, warp-local ----
    for (int c0 = 0; c0 < SWIN; c0 += 32) {
        float p[2][4][4];
#pragma unroll
        for (int mt = 0; mt < 2; mt++)
#pragma unroll
            for (int nt = 0; nt < 4; nt++)
#pragma unroll
                for (int i = 0; i < 4; i++) p[mt][nt][i] = 0.f;

        // S = Q K^T
#pragma unroll
        for (int ks = 0; ks < 4; ks++) {
            uint32_t km0[4], km1[4];
            ldsm4(km0, k_base + (uint32_t)(c0 * (QSTR * 4)) + ks * 32);        // nt 0,1
            ldsm4(km1, k_base + (uint32_t)((c0 + 16) * (QSTR * 4)) + ks * 32); // nt 2,3
#pragma unroll
            for (int mt = 0; mt < 2; mt++) {
                mma_tf32(p[mt][0], qf[mt][ks], km0);
                mma_tf32(p[mt][1], qf[mt][ks], km0 + 2);
                mma_tf32(p[mt][2], qf[mt][ks], km1);
                mma_tf32(p[mt][3], qf[mt][ks], km1 + 2);
            }
        }

        // exp (no max pass), row-sum partials, P -> smem (tf32)
#pragma unroll
        for (int mt = 0; mt < 2; mt++)
#pragma unroll
            for (int nt = 0; nt < 4; nt++) {
                float e0 = __expf(p[mt][nt][0]);
                float e1 = __expf(p[mt][nt][1]);
                float e2 = __expf(p[mt][nt][2]);
                float e3 = __expf(p[mt][nt][3]);
                rs[mt][0] += e0 + e1;
                rs[mt][1] += e2 + e3;
                uint32_t ad = p_st + mt * (16 * QSTR * 4) + nt * 32;
                sts64(ad, f2tf32(e0), f2tf32(e1));
                sts64(ad + 8 * QSTR * 4, f2tf32(e2), f2tf32(e3));
            }
        __syncwarp();

        // O += P V
#pragma unroll
        for (int kk = 0; kk < 4; kk++) {
            uint32_t pa0[4], pa1[4], vm0[4], vm1[4];
            ldsm4(pa0, a_base + kk * 32);
            ldsm4(pa1, a_base + 16 * QSTR * 4 + kk * 32);
            ldsm4(vm0, v_base + (uint32_t)((c0 + kk * 8) * 4));                    // d 0..15
            ldsm4(vm1, v_base + 16 * VTSTR * 4 + (uint32_t)((c0 + kk * 8) * 4));   // d 16..31
            mma_tf32(o[0][0], pa0, vm0);
            mma_tf32(o[0][1], pa0, vm0 + 2);
            mma_tf32(o[0][2], pa0, vm1);
            mma_tf32(o[0][3], pa0, vm1 + 2);
            mma_tf32(o[1][0], pa1, vm0);
            mma_tf32(o[1][1], pa1, vm0 + 2);
            mma_tf32(o[1][2], pa1, vm1);
            mma_tf32(o[1][3], pa1, vm1 + 2);
        }
        __syncwarp();
    }

    // ---- row-sum quad reduce + normalized O -> Qsm staging (warp-local rows) ----
#pragma unroll
    for (int mt = 0; mt < 2; mt++) {
#pragma unroll
        for (int r = 0; r < 2; r++) {
            float s = rs[mt][r];
            s += __shfl_xor_sync(0xffffffffu, s, 1);
            s += __shfl_xor_sync(0xffffffffu, s, 2);
            rs[mt][r] = 1.0f / s;
        }
#pragma unroll
        for (int nt = 0; nt < 4; nt++) {
            uint32_t ad = p_st + mt * (16 * QSTR * 4) + nt * 32;
            sts64(ad, __float_as_uint(o[mt][nt][0] * rs[mt][0]),
                      __float_as_uint(o[mt][nt][1] * rs[mt][0]));
            sts64(ad + 8 * QSTR * 4, __float_as_uint(o[mt][nt][2] * rs[mt][1]),
                                     __float_as_uint(o[mt][nt][3] * rs[mt][1]));
        }
    }
    __syncwarp();

    // ---- epilogue: O + LePE conv (from tf32 V^T) + store ----
    {
        const int s = tid;
        const int h = s >> 3, w = s & 7;
        float ov[32];
#pragma unroll
        for (int i = 0; i < 8; i++) {
            float4 t = *(const float4*)(Qsm + s * QSTR + i * 4);
            ov[i*4]   = t.x + Bsm[i*4];   ov[i*4+1] = t.y + Bsm[i*4+1];
            ov[i*4+2] = t.z + Bsm[i*4+2]; ov[i*4+3] = t.w + Bsm[i*4+3];
        }
#pragma unroll
        for (int dh = -1; dh <= 1; dh++) {
            int hh = h + dh;
            if (hh < 0 || hh >= RES) continue;
#pragma unroll
            for (int dw = -1; dw <= 1; dw++) {
                int ww = w + dw;
                if (ww < 0 || ww >= 8) continue;
                const int k = hh * 8 + ww;
                const int t = (dh + 1) * 3 + (dw + 1);
#pragma unroll
                for (int d = 0; d < 32; d++)
                    ov[d] += Wsm[d * 9 + t] * smem[VT_OFF + d * VTSTR + k];
            }
        }
        const int l = dsl * 1024 + h * 32 + iw * 8 + w;
        float* op = out + ((size_t)b * LTOK + l) * CDIM + head * HDV;
#pragma unroll
        for (int i = 0; i < 8; i++)
            *(float4*)(op + i * 4) = make_float4(ov[i*4], ov[i*4+1], ov[i*4+2], ov[i*4+3]);
    }
}

extern "C" void kernel_launch(void* const* d_in, const int* in_sizes, int n_in,
                              void* d_out, int out_size)
{
    const float* qkv    = (const float*)d_in[0];
    const float* conv_w = (const float*)d_in[1];
    const float* conv_b = (const float*)d_in[2];
    float* out = (float*)d_out;

    cudaFuncSetAttribute(lepe_attn_mma,
                         cudaFuncAttributeMaxDynamicSharedMemorySize, SMEM_BYTES);
    lepe_attn_mma<<<2048, NT, SMEM_BYTES>>>(qkv, conv_w, conv_b, out);
}

// round 6
// speedup vs baseline: 2.4875x; 1.0251x over previous
#include <cuda_runtime.h>
#include <stdint.h>

#define RES    32
#define BATCH  2
#define LTOK   32768
#define CDIM   256
#define HEADS  8
#define HDV    32
#define SWIN   256
// scale * log2(e): exp(s) == 2^(s * log2e), folded into Q pre-scale
#define SCALEE 0.25505654201513125f

#define NT     256
#define QSTR   36       // Q/K row stride (floats); 144B
#define VTSTR  260      // V^T row stride (floats); 1040B

#define QS_OFF 0                        // Q tf32 [256][36] -> P buffer -> O staging
#define KS_OFF (QS_OFF + SWIN*QSTR)     // K tf32 [256][36]
#define VT_OFF (KS_OFF + SWIN*QSTR)     // V^T tf32 [32][260]
#define W_OFF  (VT_OFF + HDV*VTSTR)     // conv w 288
#define B_OFF  (W_OFF + 9*HDV)          // conv b 32
#define SMEM_FLOATS (B_OFF + HDV)
#define SMEM_BYTES  (SMEM_FLOATS * 4)   // ~105.8 KB -> 2 blocks/SM

__device__ __forceinline__ uint32_t f2tf32(float f) {
    uint32_t r; asm("cvt.rna.tf32.f32 %0, %1;" : "=r"(r) : "f"(f)); return r;
}
__device__ __forceinline__ float ex2f(float x) {
    float r; asm("ex2.approx.f32 %0, %1;" : "=f"(r) : "f"(x)); return r;
}
__device__ __forceinline__ uint32_t smem_u32(const void* p) {
    uint32_t a;
    asm("{ .reg .u64 t; cvta.to.shared.u64 t, %1; cvt.u32.u64 %0, t; }" : "=r"(a) : "l"(p));
    return a;
}
__device__ __forceinline__ void ldsm4(uint32_t* r, uint32_t addr) {
    asm volatile("ldmatrix.sync.aligned.m8n8.x4.shared.b16 {%0,%1,%2,%3}, [%4];"
        : "=r"(r[0]), "=r"(r[1]), "=r"(r[2]), "=r"(r[3]) : "r"(addr));
}
__device__ __forceinline__ void sts64(uint32_t addr, uint32_t a, uint32_t b) {
    asm volatile("st.shared.v2.b32 [%0], {%1, %2};" :: "r"(addr), "r"(a), "r"(b) : "memory");
}
__device__ __forceinline__ void mma_tf32(float* d, const uint32_t* a, const uint32_t* b) {
    asm("mma.sync.aligned.m16n8k8.row.col.f32.tf32.tf32.f32 "
        "{%0,%1,%2,%3}, {%4,%5,%6,%7}, {%8,%9}, {%0,%1,%2,%3};"
        : "+f"(d[0]), "+f"(d[1]), "+f"(d[2]), "+f"(d[3])
        : "r"(a[0]), "r"(a[1]), "r"(a[2]), "r"(a[3]), "r"(b[0]), "r"(b[1]));
}

__global__ void __launch_bounds__(NT, 2)
lepe_attn_mma(const float* __restrict__ qkv,
              const float* __restrict__ conv_w,
              const float* __restrict__ conv_b,
              float* __restrict__ out)
{
    extern __shared__ float smem[];
    float* Qsm = smem + QS_OFF;
    float* Wsm = smem + W_OFF;
    float* Bsm = smem + B_OFF;
    const uint32_t sb = smem_u32(smem);

    const int tid  = threadIdx.x;
    const int lane = tid & 31;
    const int warp = tid >> 5;
    const int g    = lane >> 2;
    const int tg   = lane & 3;
    const int m0   = warp * 32;

    const int head = blockIdx.x & 7;
    const int wi   = blockIdx.x >> 3;
    const int b    = wi >> 7;
    const int dsl  = (wi >> 2) & 31;
    const int iw   = wi & 3;

    // ---- stage: Q (tf32, scale*log2e) ; K (tf32) ; V^T (tf32) ----
    {
        const int s = tid;
        const int l = dsl * 1024 + (s >> 3) * 32 + iw * 8 + (s & 7);
        const size_t base = ((size_t)b * LTOK + l) * CDIM + head * HDV;
        const float* qp = qkv + base;
        const float* kp = qkv + (size_t)BATCH * LTOK * CDIM + base;
        const float* vp = qkv + 2 * (size_t)BATCH * LTOK * CDIM + base;
#pragma unroll
        for (int i = 0; i < 8; i++) {
            float4 qq = *(const float4*)(qp + i * 4);
            *(uint4*)(smem + QS_OFF + s * QSTR + i * 4) = make_uint4(
                f2tf32(qq.x * SCALEE), f2tf32(qq.y * SCALEE),
                f2tf32(qq.z * SCALEE), f2tf32(qq.w * SCALEE));
            float4 kk = *(const float4*)(kp + i * 4);
            *(uint4*)(smem + KS_OFF + s * QSTR + i * 4) = make_uint4(
                f2tf32(kk.x), f2tf32(kk.y), f2tf32(kk.z), f2tf32(kk.w));
            float4 vv = *(const float4*)(vp + i * 4);
            ((uint32_t*)smem)[VT_OFF + (i*4+0) * VTSTR + s] = f2tf32(vv.x);
            ((uint32_t*)smem)[VT_OFF + (i*4+1) * VTSTR + s] = f2tf32(vv.y);
            ((uint32_t*)smem)[VT_OFF + (i*4+2) * VTSTR + s] = f2tf32(vv.z);
            ((uint32_t*)smem)[VT_OFF + (i*4+3) * VTSTR + s] = f2tf32(vv.w);
        }
        for (int i = tid; i < 9 * HDV; i += NT) Wsm[i] = conv_w[head * HDV * 9 + i];
        if (tid < HDV) Bsm[tid] = conv_b[head * HDV + tid];
    }
    __syncthreads();

    const int lane7 = lane & 7;
    const int lb8   = (lane >> 3) & 1;
    const int lb16  = (lane >> 4) & 1;
    const uint32_t a_base = sb + (QS_OFF + (m0 + lane7 + lb8 * 8) * QSTR) * 4 + lb16 * 16;
    const uint32_t k_base = sb + (KS_OFF + (lane7 + lb16 * 8) * QSTR) * 4 + lb8 * 16;
    const uint32_t v_base = sb + (VT_OFF + (lane7 + lb16 * 8) * VTSTR) * 4 + lb8 * 16;
    const uint32_t p_st   = sb + (QS_OFF + (m0 + g) * QSTR + 2 * tg) * 4;

    // ---- Q fragments ----
    uint32_t qf[2][4][4];
#pragma unroll
    for (int mt = 0; mt < 2; mt++)
#pragma unroll
        for (int ks = 0; ks < 4; ks++)
            ldsm4(qf[mt][ks], a_base + mt * (16 * QSTR * 4) + ks * 32);

    float o[2][4][4];
    float rs[2][2];
#pragma unroll
    for (int mt = 0; mt < 2; mt++) {
        rs[mt][0] = 0.f; rs[mt][1] = 0.f;
#pragma unroll
        for (int nt = 0; nt < 4; nt++)
#pragma unroll
            for (int i = 0; i < 4; i++) o[mt][nt][i] = 0.f;
    }
    __syncwarp();

    // ---- main loop: 8 chunks of 32 keys ----
    for (int c0 = 0; c0 < SWIN; c0 += 32) {
        float p[2][4][4];
#pragma unroll
        for (int mt = 0; mt < 2; mt++)
#pragma unroll
            for (int nt = 0; nt < 4; nt++)
#pragma unroll
                for (int i = 0; i < 4; i++) p[mt][nt][i] = 0.f;

        // S = Q K^T : ldsm in batches of 4 (ks pair), then 16 MMAs
#pragma unroll
        for (int kp2 = 0; kp2 < 2; kp2++) {
            uint32_t km[4][4];   // [ks-half(2)][ntile-pair(2)] -> 4 ldsm.x4
            ldsm4(km[0], k_base + (uint32_t)(c0 * (QSTR * 4)) + (kp2 * 2 + 0) * 32);
            ldsm4(km[1], k_base + (uint32_t)((c0 + 16) * (QSTR * 4)) + (kp2 * 2 + 0) * 32);
            ldsm4(km[2], k_base + (uint32_t)(c0 * (QSTR * 4)) + (kp2 * 2 + 1) * 32);
            ldsm4(km[3], k_base + (uint32_t)((c0 + 16) * (QSTR * 4)) + (kp2 * 2 + 1) * 32);
#pragma unroll
            for (int kh = 0; kh < 2; kh++) {
                const int ks = kp2 * 2 + kh;
#pragma unroll
                for (int mt = 0; mt < 2; mt++) {
                    mma_tf32(p[mt][0], qf[mt][ks], km[kh * 2]);
                    mma_tf32(p[mt][1], qf[mt][ks], km[kh * 2] + 2);
                    mma_tf32(p[mt][2], qf[mt][ks], km[kh * 2 + 1]);
                    mma_tf32(p[mt][3], qf[mt][ks], km[kh * 2 + 1] + 2);
                }
            }
        }

        // p = 2^s (bare ex2), row-sum partials, P -> smem (tf32)
#pragma unroll
        for (int mt = 0; mt < 2; mt++)
#pragma unroll
            for (int nt = 0; nt < 4; nt++) {
                float e0 = ex2f(p[mt][nt][0]);
                float e1 = ex2f(p[mt][nt][1]);
                float e2 = ex2f(p[mt][nt][2]);
                float e3 = ex2f(p[mt][nt][3]);
                rs[mt][0] += e0 + e1;
                rs[mt][1] += e2 + e3;
                uint32_t ad = p_st + mt * (16 * QSTR * 4) + nt * 32;
                sts64(ad, f2tf32(e0), f2tf32(e1));
                sts64(ad + 8 * QSTR * 4, f2tf32(e2), f2tf32(e3));
            }
        __syncwarp();

        // O += P V : 8 ldsm (two kk steps) then 16 MMAs
#pragma unroll
        for (int kkp = 0; kkp < 2; kkp++) {
            uint32_t pa[2][8], vm[2][8];
#pragma unroll
            for (int u = 0; u < 2; u++) {
                const int kk = kkp * 2 + u;
                ldsm4(pa[u],     a_base + kk * 32);
                ldsm4(pa[u] + 4, a_base + 16 * QSTR * 4 + kk * 32);
                ldsm4(vm[u],     v_base + (uint32_t)((c0 + kk * 8) * 4));
                ldsm4(vm[u] + 4, v_base + 16 * VTSTR * 4 + (uint32_t)((c0 + kk * 8) * 4));
            }
#pragma unroll
            for (int u = 0; u < 2; u++) {
#pragma unroll
                for (int mt = 0; mt < 2; mt++) {
                    mma_tf32(o[mt][0], pa[u] + mt * 4, vm[u]);
                    mma_tf32(o[mt][1], pa[u] + mt * 4, vm[u] + 2);
                    mma_tf32(o[mt][2], pa[u] + mt * 4, vm[u] + 4);
                    mma_tf32(o[mt][3], pa[u] + mt * 4, vm[u] + 6);
                }
            }
        }
        __syncwarp();
    }

    // ---- row-sum quad reduce + normalized O -> staging ----
#pragma unroll
    for (int mt = 0; mt < 2; mt++) {
#pragma unroll
        for (int r = 0; r < 2; r++) {
            float s = rs[mt][r];
            s += __shfl_xor_sync(0xffffffffu, s, 1);
            s += __shfl_xor_sync(0xffffffffu, s, 2);
            rs[mt][r] = 1.0f / s;
        }
#pragma unroll
        for (int nt = 0; nt < 4; nt++) {
            uint32_t ad = p_st + mt * (16 * QSTR * 4) + nt * 32;
            sts64(ad, __float_as_uint(o[mt][nt][0] * rs[mt][0]),
                      __float_as_uint(o[mt][nt][1] * rs[mt][0]));
            sts64(ad + 8 * QSTR * 4, __float_as_uint(o[mt][nt][2] * rs[mt][1]),
                                     __float_as_uint(o[mt][nt][3] * rs[mt][1]));
        }
    }
    __syncwarp();

    // ---- epilogue: O + LePE conv (tf32 V^T) + store ----
    {
        const int s = tid;
        const int h = s >> 3, w = s & 7;
        float ov[32];
#pragma unroll
        for (int i = 0; i < 8; i++) {
            float4 t = *(const float4*)(Qsm + s * QSTR + i * 4);
            ov[i*4]   = t.x + Bsm[i*4];   ov[i*4+1] = t.y + Bsm[i*4+1];
            ov[i*4+2] = t.z + Bsm[i*4+2]; ov[i*4+3] = t.w + Bsm[i*4+3];
        }
#pragma unroll
        for (int dh = -1; dh <= 1; dh++) {
            int hh = h + dh;
            if (hh < 0 || hh >= RES) continue;
#pragma unroll
            for (int dw = -1; dw <= 1; dw++) {
                int ww = w + dw;
                if (ww < 0 || ww >= 8) continue;
                const int k = hh * 8 + ww;
                const int t = (dh + 1) * 3 + (dw + 1);
#pragma unroll
                for (int d = 0; d < 32; d++)
                    ov[d] += Wsm[d * 9 + t] * smem[VT_OFF + d * VTSTR + k];
            }
        }
        const int l = dsl * 1024 + h * 32 + iw * 8 + w;
        float* op = out + ((size_t)b * LTOK + l) * CDIM + head * HDV;
#pragma unroll
        for (int i = 0; i < 8; i++)
            *(float4*)(op + i * 4) = make_float4(ov[i*4], ov[i*4+1], ov[i*4+2], ov[i*4+3]);
    }
}

extern "C" void kernel_launch(void* const* d_in, const int* in_sizes, int n_in,
                              void* d_out, int out_size)
{
    const float* qkv    = (const float*)d_in[0];
    const float* conv_w = (const float*)d_in[1];
    const float* conv_b = (const float*)d_in[2];
    float* out = (float*)d_out;

    cudaFuncSetAttribute(lepe_attn_mma,
                         cudaFuncAttributeMaxDynamicSharedMemorySize, SMEM_BYTES);
    lepe_attn_mma<<<2048, NT, SMEM_BYTES>>>(qkv, conv_w, conv_b, out);
}

// round 8
// speedup vs baseline: 4.2199x; 1.6964x over previous
#include <cuda_runtime.h>
#include <cuda_fp16.h>
#include <stdint.h>

#define RES    32
#define BATCH  2
#define LTOK   32768
#define CDIM   256
#define HEADS  8
#define HDV    32
#define SWIN   256
// scale * log2(e): exp(s) == 2^(s*log2e), folded into Q pre-scale
#define SCALEE 0.25505654201513125f

#define NT     256
// fp16 tile rows: 40 halves = 80B stride
#define HSTR_B 80

// byte offsets in smem
#define QS_B   0        // Q fp16 [256][40] -> P buffer; O staging overlays QS+KS
#define KS_B   20480    // K fp16 [256][40]
#define VS_B   40960    // V fp16 [256][40]
#define W_B    61440    // conv w, 288 fp32
#define BI_B   62592    // conv b, 32 fp32
#define SMEM_BYTES 62720
// O staging: fp32 [256][36] overlaid on QS_B.. (36,864B; spills into KS region,
// so a __syncthreads() must separate main-loop K reads from staging writes)
#define OSTR   36

__device__ __forceinline__ float ex2f(float x) {
    float r; asm("ex2.approx.f32 %0, %1;" : "=f"(r) : "f"(x)); return r;
}
__device__ __forceinline__ uint32_t h2u(__half2 h) {
    return *reinterpret_cast<uint32_t*>(&h);
}
__device__ __forceinline__ uint32_t smem_u32(const void* p) {
    uint32_t a;
    asm("{ .reg .u64 t; cvta.to.shared.u64 t, %1; cvt.u32.u64 %0, t; }" : "=r"(a) : "l"(p));
    return a;
}
__device__ __forceinline__ void ldsm4(uint32_t* r, uint32_t addr) {
    asm volatile("ldmatrix.sync.aligned.m8n8.x4.shared.b16 {%0,%1,%2,%3}, [%4];"
        : "=r"(r[0]), "=r"(r[1]), "=r"(r[2]), "=r"(r[3]) : "r"(addr));
}
__device__ __forceinline__ void ldsm4t(uint32_t* r, uint32_t addr) {
    asm volatile("ldmatrix.sync.aligned.m8n8.x4.trans.shared.b16 {%0,%1,%2,%3}, [%4];"
        : "=r"(r[0]), "=r"(r[1]), "=r"(r[2]), "=r"(r[3]) : "r"(addr));
}
__device__ __forceinline__ void sts32(uint32_t addr, uint32_t v) {
    asm volatile("st.shared.b32 [%0], %1;" :: "r"(addr), "r"(v) : "memory");
}
__device__ __forceinline__ void sts64(uint32_t addr, uint32_t a, uint32_t b) {
    asm volatile("st.shared.v2.b32 [%0], {%1, %2};" :: "r"(addr), "r"(a), "r"(b) : "memory");
}
// D(f32) += A(f16) * B(f16),  m16n8k16
__device__ __forceinline__ void mma16(float* d, const uint32_t* a, const uint32_t* b) {
    asm("mma.sync.aligned.m16n8k16.row.col.f32.f16.f16.f32 "
        "{%0,%1,%2,%3}, {%4,%5,%6,%7}, {%8,%9}, {%0,%1,%2,%3};"
        : "+f"(d[0]), "+f"(d[1]), "+f"(d[2]), "+f"(d[3])
        : "r"(a[0]), "r"(a[1]), "r"(a[2]), "r"(a[3]), "r"(b[0]), "r"(b[1]));
}

__global__ void __launch_bounds__(NT, 2)
lepe_attn_h16(const float* __restrict__ qkv,
              const float* __restrict__ conv_w,
              const float* __restrict__ conv_b,
              float* __restrict__ out)
{
    extern __shared__ float smem[];
    char* smb = (char*)smem;
    float* Wsm = (float*)(smb + W_B);
    float* Bsm = (float*)(smb + BI_B);
    const uint32_t sb = smem_u32(smem);

    const int tid  = threadIdx.x;
    const int lane = tid & 31;
    const int warp = tid >> 5;
    const int g    = lane >> 2;
    const int tg   = lane & 3;
    const int m0   = warp * 32;

    const int head = blockIdx.x & 7;
    const int wi   = blockIdx.x >> 3;
    const int b    = wi >> 7;
    const int dsl  = (wi >> 2) & 31;
    const int iw   = wi & 3;

    // ---- stage Q (fp16, *scale*log2e), K (fp16), V (fp16, [key][d]) ----
    {
        const int s = tid;
        const int l = dsl * 1024 + (s >> 3) * 32 + iw * 8 + (s & 7);
        const size_t base = ((size_t)b * LTOK + l) * CDIM + head * HDV;
        const float* qp = qkv + base;
        const float* kp = qkv + (size_t)BATCH * LTOK * CDIM + base;
        const float* vp = qkv + 2 * (size_t)BATCH * LTOK * CDIM + base;
#pragma unroll
        for (int i = 0; i < 8; i++) {
            float4 qq = *(const float4*)(qp + i * 4);
            *(uint2*)(smb + QS_B + s * HSTR_B + i * 8) = make_uint2(
                h2u(__floats2half2_rn(qq.x * SCALEE, qq.y * SCALEE)),
                h2u(__floats2half2_rn(qq.z * SCALEE, qq.w * SCALEE)));
            float4 kk = *(const float4*)(kp + i * 4);
            *(uint2*)(smb + KS_B + s * HSTR_B + i * 8) = make_uint2(
                h2u(__floats2half2_rn(kk.x, kk.y)),
                h2u(__floats2half2_rn(kk.z, kk.w)));
            float4 vv = *(const float4*)(vp + i * 4);
            *(uint2*)(smb + VS_B + s * HSTR_B + i * 8) = make_uint2(
                h2u(__floats2half2_rn(vv.x, vv.y)),
                h2u(__floats2half2_rn(vv.z, vv.w)));
        }
        for (int i = tid; i < 9 * HDV; i += NT) Wsm[i] = conv_w[head * HDV * 9 + i];
        if (tid < HDV) Bsm[tid] = conv_b[head * HDV + tid];
    }
    __syncthreads();

    const int lane7 = lane & 7;
    const int lb8   = (lane >> 3) & 1;
    const int lb16  = (lane >> 4) & 1;
    // A-pattern (Q, P): rows (m0 + lane7 + lb8*8), k-col half lb16*16B
    const uint32_t a_base = sb + QS_B + (uint32_t)(m0 + lane7 + lb8 * 8) * HSTR_B + lb16 * 16;
    // B-pattern (K): rows (key lane7 + lb16*8), k-col half lb8*16B
    const uint32_t k_base = sb + KS_B + (uint32_t)(lane7 + lb16 * 8) * HSTR_B + lb8 * 16;
    // B-trans pattern (V): rows (key lane7 + lb8*8), d-col half lb16*16B
    const uint32_t v_base = sb + VS_B + (uint32_t)(lane7 + lb8 * 8) * HSTR_B + lb16 * 16;
    // P store: half2 at row (m0+g), col (nt*8 + 2tg)
    const uint32_t p_st = sb + QS_B + (uint32_t)(m0 + g) * HSTR_B + 4 * tg;
    // O staging (fp32, stride 36): row (m0+g), col 2tg
    const uint32_t o_st = sb + QS_B + ((uint32_t)(m0 + g) * OSTR + 2 * tg) * 4;

    // ---- Q fragments: 2 m-tiles x 2 k-steps ----
    uint32_t qf[2][2][4];
#pragma unroll
    for (int mt = 0; mt < 2; mt++)
#pragma unroll
        for (int ks = 0; ks < 2; ks++)
            ldsm4(qf[mt][ks], a_base + mt * (16 * HSTR_B) + ks * 32);
    __syncwarp();

    float o[2][4][4];
    float rs[2][2];
#pragma unroll
    for (int mt = 0; mt < 2; mt++) {
        rs[mt][0] = 0.f; rs[mt][1] = 0.f;
#pragma unroll
        for (int nt = 0; nt < 4; nt++)
#pragma unroll
            for (int i = 0; i < 4; i++) o[mt][nt][i] = 0.f;
    }

    // ---- main loop: 8 chunks of 32 keys, warp-local ----
    for (int c0 = 0; c0 < SWIN; c0 += 32) {
        float p[2][4][4];
#pragma unroll
        for (int mt = 0; mt < 2; mt++)
#pragma unroll
            for (int nt = 0; nt < 4; nt++)
#pragma unroll
                for (int i = 0; i < 4; i++) p[mt][nt][i] = 0.f;

        // S = Q K^T
#pragma unroll
        for (int ks = 0; ks < 2; ks++) {
            uint32_t kf0[4], kf1[4];
            ldsm4(kf0, k_base + (uint32_t)(c0 * HSTR_B) + ks * 32);          // keys c0..+15
            ldsm4(kf1, k_base + (uint32_t)((c0 + 16) * HSTR_B) + ks * 32);   // keys +16..+31
#pragma unroll
            for (int mt = 0; mt < 2; mt++) {
                mma16(p[mt][0], qf[mt][ks], kf0);
                mma16(p[mt][1], qf[mt][ks], kf0 + 2);
                mma16(p[mt][2], qf[mt][ks], kf1);
                mma16(p[mt][3], qf[mt][ks], kf1 + 2);
            }
        }

        // p = 2^s, row-sum partials, P -> smem (fp16 pairs)
#pragma unroll
        for (int mt = 0; mt < 2; mt++)
#pragma unroll
            for (int nt = 0; nt < 4; nt++) {
                float e0 = ex2f(p[mt][nt][0]);
                float e1 = ex2f(p[mt][nt][1]);
                float e2 = ex2f(p[mt][nt][2]);
                float e3 = ex2f(p[mt][nt][3]);
                rs[mt][0] += e0 + e1;
                rs[mt][1] += e2 + e3;
                uint32_t ad = p_st + mt * (16 * HSTR_B) + nt * 16;
                sts32(ad, h2u(__floats2half2_rn(e0, e1)));
                sts32(ad + 8 * HSTR_B, h2u(__floats2half2_rn(e2, e3)));
            }
        __syncwarp();

        // O += P V
#pragma unroll
        for (int ks = 0; ks < 2; ks++) {
            uint32_t pf0[4], pf1[4], vf0[4], vf1[4];
            ldsm4(pf0, a_base + ks * 32);
            ldsm4(pf1, a_base + 16 * HSTR_B + ks * 32);
            ldsm4t(vf0, v_base + (uint32_t)((c0 + ks * 16) * HSTR_B));        // d 0-15
            ldsm4t(vf1, v_base + (uint32_t)((c0 + ks * 16) * HSTR_B) + 32);   // d 16-31
            mma16(o[0][0], pf0, vf0);
            mma16(o[0][1], pf0, vf0 + 2);
            mma16(o[0][2], pf0, vf1);
            mma16(o[0][3], pf0, vf1 + 2);
            mma16(o[1][0], pf1, vf0);
            mma16(o[1][1], pf1, vf0 + 2);
            mma16(o[1][2], pf1, vf1);
            mma16(o[1][3], pf1, vf1 + 2);
        }
        __syncwarp();
    }

    // All warps must finish reading K/Q smem before O staging overwrites them.
    __syncthreads();

    // ---- row-sum quad reduce + normalized O -> fp32 staging (over Q+K region) ----
#pragma unroll
    for (int mt = 0; mt < 2; mt++) {
#pragma unroll
        for (int r = 0; r < 2; r++) {
            float s = rs[mt][r];
            s += __shfl_xor_sync(0xffffffffu, s, 1);
            s += __shfl_xor_sync(0xffffffffu, s, 2);
            rs[mt][r] = 1.0f / s;
        }
#pragma unroll
        for (int nt = 0; nt < 4; nt++) {
            uint32_t ad = o_st + (mt * 16 * OSTR + nt * 8) * 4;
            sts64(ad, __float_as_uint(o[mt][nt][0] * rs[mt][0]),
                      __float_as_uint(o[mt][nt][1] * rs[mt][0]));
            sts64(ad + 8 * OSTR * 4, __float_as_uint(o[mt][nt][2] * rs[mt][1]),
                                     __float_as_uint(o[mt][nt][3] * rs[mt][1]));
        }
    }
    __syncwarp();

    // ---- epilogue: O + LePE conv (fp16 V) + store ----
    {
        const int s = tid;
        const int h = s >> 3, w = s & 7;
        float ov[32];
#pragma unroll
        for (int i = 0; i < 8; i++) {
            float4 t = *(const float4*)(smb + QS_B + s * (OSTR * 4) + i * 16);
            ov[i*4]   = t.x + Bsm[i*4];   ov[i*4+1] = t.y + Bsm[i*4+1];
            ov[i*4+2] = t.z + Bsm[i*4+2]; ov[i*4+3] = t.w + Bsm[i*4+3];
        }
#pragma unroll
        for (int dh = -1; dh <= 1; dh++) {
            int hh = h + dh;
            if (hh < 0 || hh >= RES) continue;
#pragma unroll
            for (int dw = -1; dw <= 1; dw++) {
                int ww = w + dw;
                if (ww < 0 || ww >= 8) continue;
                const int k = hh * 8 + ww;
                const int t = (dh + 1) * 3 + (dw + 1);
                const char* vrow = smb + VS_B + k * HSTR_B;
#pragma unroll
                for (int d2 = 0; d2 < 16; d2++) {
                    float2 fv = __half22float2(*(const __half2*)(vrow + d2 * 4));
                    ov[2*d2]   += Wsm[(2*d2) * 9 + t]   * fv.x;
                    ov[2*d2+1] += Wsm[(2*d2+1) * 9 + t] * fv.y;
                }
            }
        }
        const int l = dsl * 1024 + h * 32 + iw * 8 + w;
        float* op = out + ((size_t)b * LTOK + l) * CDIM + head * HDV;
#pragma unroll
        for (int i = 0; i < 8; i++)
            *(float4*)(op + i * 4) = make_float4(ov[i*4], ov[i*4+1], ov[i*4+2], ov[i*4+3]);
    }
}

extern "C" void kernel_launch(void* const* d_in, const int* in_sizes, int n_in,
                              void* d_out, int out_size)
{
    const float* qkv    = (const float*)d_in[0];
    const float* conv_w = (const float*)d_in[1];
    const float* conv_b = (const float*)d_in[2];
    float* out = (float*)d_out;

    cudaFuncSetAttribute(lepe_attn_h16,
                         cudaFuncAttributeMaxDynamicSharedMemorySize, SMEM_BYTES);
    lepe_attn_h16<<<2048, NT, SMEM_BYTES>>>(qkv, conv_w, conv_b, out);
}

// round 9
// speedup vs baseline: 4.6889x; 1.1111x over previous
#include <cuda_runtime.h>
#include <cuda_fp16.h>
#include <stdint.h>

#define RES    32
#define BATCH  2
#define LTOK   32768
#define CDIM   256
#define HEADS  8
#define HDV    32
#define SWIN   256
// scale * log2(e): exp(s) == 2^(s*log2e), folded into Q pre-scale
#define SCALEE 0.25505654201513125f

#define NT     256
#define HSTR_B 80      // fp16 tile row stride: 40 halves = 80B

// byte offsets in smem
#define QS_B   0        // Q fp16 [256][40]; O staging overlays QS+KS
#define KS_B   20480    // K fp16 [256][40]
#define VS_B   40960    // V fp16 [256][40]
#define W_B    61440    // conv w, 288 fp32
#define BI_B   62592    // conv b, 32 fp32
#define SMEM_BYTES 62720
// O staging: fp32 [256][36] overlaid on QS_B.. (spills into KS region ->
// __syncthreads() must separate main-loop K reads from staging writes)
#define OSTR   36

__device__ __forceinline__ float ex2f(float x) {
    float r; asm("ex2.approx.f32 %0, %1;" : "=f"(r) : "f"(x)); return r;
}
__device__ __forceinline__ uint32_t h2u(__half2 h) {
    return *reinterpret_cast<uint32_t*>(&h);
}
__device__ __forceinline__ uint32_t smem_u32(const void* p) {
    uint32_t a;
    asm("{ .reg .u64 t; cvta.to.shared.u64 t, %1; cvt.u32.u64 %0, t; }" : "=r"(a) : "l"(p));
    return a;
}
__device__ __forceinline__ void ldsm4(uint32_t* r, uint32_t addr) {
    asm volatile("ldmatrix.sync.aligned.m8n8.x4.shared.b16 {%0,%1,%2,%3}, [%4];"
        : "=r"(r[0]), "=r"(r[1]), "=r"(r[2]), "=r"(r[3]) : "r"(addr));
}
__device__ __forceinline__ void ldsm4t(uint32_t* r, uint32_t addr) {
    asm volatile("ldmatrix.sync.aligned.m8n8.x4.trans.shared.b16 {%0,%1,%2,%3}, [%4];"
        : "=r"(r[0]), "=r"(r[1]), "=r"(r[2]), "=r"(r[3]) : "r"(addr));
}
__device__ __forceinline__ void sts64(uint32_t addr, uint32_t a, uint32_t b) {
    asm volatile("st.shared.v2.b32 [%0], {%1, %2};" :: "r"(addr), "r"(a), "r"(b) : "memory");
}
// D(f32) += A(f16) * B(f16),  m16n8k16
__device__ __forceinline__ void mma16(float* d, const uint32_t* a, const uint32_t* b) {
    asm("mma.sync.aligned.m16n8k16.row.col.f32.f16.f16.f32 "
        "{%0,%1,%2,%3}, {%4,%5,%6,%7}, {%8,%9}, {%0,%1,%2,%3};"
        : "+f"(d[0]), "+f"(d[1]), "+f"(d[2]), "+f"(d[3])
        : "r"(a[0]), "r"(a[1]), "r"(a[2]), "r"(a[3]), "r"(b[0]), "r"(b[1]));
}

__global__ void __launch_bounds__(NT, 2)
lepe_attn_h16(const float* __restrict__ qkv,
              const float* __restrict__ conv_w,
              const float* __restrict__ conv_b,
              float* __restrict__ out)
{
    extern __shared__ float smem[];
    char* smb = (char*)smem;
    float* Wsm = (float*)(smb + W_B);
    float* Bsm = (float*)(smb + BI_B);
    const uint32_t sb = smem_u32(smem);

    const int tid  = threadIdx.x;
    const int lane = tid & 31;
    const int warp = tid >> 5;
    const int g    = lane >> 2;
    const int tg   = lane & 3;
    const int m0   = warp * 32;

    const int head = blockIdx.x & 7;
    const int wi   = blockIdx.x >> 3;
    const int b    = wi >> 7;
    const int dsl  = (wi >> 2) & 31;
    const int iw   = wi & 3;

    // ---- stage Q (fp16, *scale*log2e), K (fp16), V (fp16, [key][d]) ----
    {
        const int s = tid;
        const int l = dsl * 1024 + (s >> 3) * 32 + iw * 8 + (s & 7);
        const size_t base = ((size_t)b * LTOK + l) * CDIM + head * HDV;
        const float* qp = qkv + base;
        const float* kp = qkv + (size_t)BATCH * LTOK * CDIM + base;
        const float* vp = qkv + 2 * (size_t)BATCH * LTOK * CDIM + base;
#pragma unroll
        for (int i = 0; i < 8; i++) {
            float4 qq = *(const float4*)(qp + i * 4);
            *(uint2*)(smb + QS_B + s * HSTR_B + i * 8) = make_uint2(
                h2u(__floats2half2_rn(qq.x * SCALEE, qq.y * SCALEE)),
                h2u(__floats2half2_rn(qq.z * SCALEE, qq.w * SCALEE)));
            float4 kk = *(const float4*)(kp + i * 4);
            *(uint2*)(smb + KS_B + s * HSTR_B + i * 8) = make_uint2(
                h2u(__floats2half2_rn(kk.x, kk.y)),
                h2u(__floats2half2_rn(kk.z, kk.w)));
            float4 vv = *(const float4*)(vp + i * 4);
            *(uint2*)(smb + VS_B + s * HSTR_B + i * 8) = make_uint2(
                h2u(__floats2half2_rn(vv.x, vv.y)),
                h2u(__floats2half2_rn(vv.z, vv.w)));
        }
        for (int i = tid; i < 9 * HDV; i += NT) Wsm[i] = conv_w[head * HDV * 9 + i];
        if (tid < HDV) Bsm[tid] = conv_b[head * HDV + tid];
    }
    __syncthreads();

    const int lane7 = lane & 7;
    const int lb8   = (lane >> 3) & 1;
    const int lb16  = (lane >> 4) & 1;
    // A-pattern (Q): rows (m0 + lane7 + lb8*8), k-col half lb16*16B
    const uint32_t a_base = sb + QS_B + (uint32_t)(m0 + lane7 + lb8 * 8) * HSTR_B + lb16 * 16;
    // B-pattern (K): rows (key lane7 + lb16*8), k-col half lb8*16B
    const uint32_t k_base = sb + KS_B + (uint32_t)(lane7 + lb16 * 8) * HSTR_B + lb8 * 16;
    // B-trans pattern (V): rows (key lane7 + lb8*8), d-col half lb16*16B
    const uint32_t v_base = sb + VS_B + (uint32_t)(lane7 + lb8 * 8) * HSTR_B + lb16 * 16;
    // O staging (fp32, stride 36): row (m0+g), col 2tg
    const uint32_t o_st = sb + QS_B + ((uint32_t)(m0 + g) * OSTR + 2 * tg) * 4;

    // ---- Q fragments: 2 m-tiles x 2 k-steps ----
    uint32_t qf[2][2][4];
#pragma unroll
    for (int mt = 0; mt < 2; mt++)
#pragma unroll
        for (int ks = 0; ks < 2; ks++)
            ldsm4(qf[mt][ks], a_base + mt * (16 * HSTR_B) + ks * 32);

    float o[2][4][4];
    float rs[2][2];
#pragma unroll
    for (int mt = 0; mt < 2; mt++) {
        rs[mt][0] = 0.f; rs[mt][1] = 0.f;
#pragma unroll
        for (int nt = 0; nt < 4; nt++)
#pragma unroll
            for (int i = 0; i < 4; i++) o[mt][nt][i] = 0.f;
    }

    // ---- main loop: 8 chunks of 32 keys, fully register-local softmax ----
    for (int c0 = 0; c0 < SWIN; c0 += 32) {
        float p[2][4][4];
#pragma unroll
        for (int mt = 0; mt < 2; mt++)
#pragma unroll
            for (int nt = 0; nt < 4; nt++)
#pragma unroll
                for (int i = 0; i < 4; i++) p[mt][nt][i] = 0.f;

        // S = Q K^T
#pragma unroll
        for (int ks = 0; ks < 2; ks++) {
            uint32_t kf0[4], kf1[4];
            ldsm4(kf0, k_base + (uint32_t)(c0 * HSTR_B) + ks * 32);          // keys c0..+15
            ldsm4(kf1, k_base + (uint32_t)((c0 + 16) * HSTR_B) + ks * 32);   // keys +16..+31
#pragma unroll
            for (int mt = 0; mt < 2; mt++) {
                mma16(p[mt][0], qf[mt][ks], kf0);
                mma16(p[mt][1], qf[mt][ks], kf0 + 2);
                mma16(p[mt][2], qf[mt][ks], kf1);
                mma16(p[mt][3], qf[mt][ks], kf1 + 2);
            }
        }

        // p = 2^s; C-frag of S == A-frag of P (m16n8k16): pack directly.
        // af[mt][ks]: a0=(c0,c1|nt=2ks) a1=(c2,c3|nt=2ks) a2=(c0,c1|nt=2ks+1) a3=(c2,c3|nt=2ks+1)
        uint32_t af[2][2][4];
#pragma unroll
        for (int mt = 0; mt < 2; mt++)
#pragma unroll
            for (int nt = 0; nt < 4; nt++) {
                float e0 = ex2f(p[mt][nt][0]);
                float e1 = ex2f(p[mt][nt][1]);
                float e2 = ex2f(p[mt][nt][2]);
                float e3 = ex2f(p[mt][nt][3]);
                rs[mt][0] += e0 + e1;
                rs[mt][1] += e2 + e3;
                af[mt][nt >> 1][(nt & 1) * 2 + 0] = h2u(__floats2half2_rn(e0, e1));
                af[mt][nt >> 1][(nt & 1) * 2 + 1] = h2u(__floats2half2_rn(e2, e3));
            }

        // O += P V
#pragma unroll
        for (int ks = 0; ks < 2; ks++) {
            uint32_t vf0[4], vf1[4];
            ldsm4t(vf0, v_base + (uint32_t)((c0 + ks * 16) * HSTR_B));        // d 0-15
            ldsm4t(vf1, v_base + (uint32_t)((c0 + ks * 16) * HSTR_B) + 32);   // d 16-31
#pragma unroll
            for (int mt = 0; mt < 2; mt++) {
                mma16(o[mt][0], af[mt][ks], vf0);
                mma16(o[mt][1], af[mt][ks], vf0 + 2);
                mma16(o[mt][2], af[mt][ks], vf1);
                mma16(o[mt][3], af[mt][ks], vf1 + 2);
            }
        }
    }

    // All warps must finish reading K/Q smem before O staging overwrites them.
    __syncthreads();

    // ---- row-sum quad reduce + normalized O -> fp32 staging (over Q+K region) ----
#pragma unroll
    for (int mt = 0; mt < 2; mt++) {
#pragma unroll
        for (int r = 0; r < 2; r++) {
            float s = rs[mt][r];
            s += __shfl_xor_sync(0xffffffffu, s, 1);
            s += __shfl_xor_sync(0xffffffffu, s, 2);
            rs[mt][r] = 1.0f / s;
        }
#pragma unroll
        for (int nt = 0; nt < 4; nt++) {
            uint32_t ad = o_st + (mt * 16 * OSTR + nt * 8) * 4;
            sts64(ad, __float_as_uint(o[mt][nt][0] * rs[mt][0]),
                      __float_as_uint(o[mt][nt][1] * rs[mt][0]));
            sts64(ad + 8 * OSTR * 4, __float_as_uint(o[mt][nt][2] * rs[mt][1]),
                                     __float_as_uint(o[mt][nt][3] * rs[mt][1]));
        }
    }
    __syncthreads();

    // ---- epilogue: O + LePE conv (fp16 V) + store ----
    {
        const int s = tid;
        const int h = s >> 3, w = s & 7;
        float ov[32];
#pragma unroll
        for (int i = 0; i < 8; i++) {
            float4 t = *(const float4*)(smb + QS_B + s * (OSTR * 4) + i * 16);
            ov[i*4]   = t.x + Bsm[i*4];   ov[i*4+1] = t.y + Bsm[i*4+1];
            ov[i*4+2] = t.z + Bsm[i*4+2]; ov[i*4+3] = t.w + Bsm[i*4+3];
        }
#pragma unroll
        for (int dh = -1; dh <= 1; dh++) {
            int hh = h + dh;
            if (hh < 0 || hh >= RES) continue;
#pragma unroll
            for (int dw = -1; dw <= 1; dw++) {
                int ww = w + dw;
                if (ww < 0 || ww >= 8) continue;
                const int k = hh * 8 + ww;
                const int t = (dh + 1) * 3 + (dw + 1);
                const char* vrow = smb + VS_B + k * HSTR_B;
#pragma unroll
                for (int d2 = 0; d2 < 16; d2++) {
                    float2 fv = __half22float2(*(const __half2*)(vrow + d2 * 4));
                    ov[2*d2]   += Wsm[(2*d2) * 9 + t]   * fv.x;
                    ov[2*d2+1] += Wsm[(2*d2+1) * 9 + t] * fv.y;
                }
            }
        }
        const int l = dsl * 1024 + h * 32 + iw * 8 + w;
        float* op = out + ((size_t)b * LTOK + l) * CDIM + head * HDV;
#pragma unroll
        for (int i = 0; i < 8; i++)
            *(float4*)(op + i * 4) = make_float4(ov[i*4], ov[i*4+1], ov[i*4+2], ov[i*4+3]);
    }
}

extern "C" void kernel_launch(void* const* d_in, const int* in_sizes, int n_in,
                              void* d_out, int out_size)
{
    const float* qkv    = (const float*)d_in[0];
    const float* conv_w = (const float*)d_in[1];
    const float* conv_b = (const float*)d_in[2];
    float* out = (float*)d_out;

    cudaFuncSetAttribute(lepe_attn_h16,
                         cudaFuncAttributeMaxDynamicSharedMemorySize, SMEM_BYTES);
    lepe_attn_h16<<<2048, NT, SMEM_BYTES>>>(qkv, conv_w, conv_b, out);
}

// round 10
// speedup vs baseline: 7.1276x; 1.5201x over previous
#include <cuda_runtime.h>
#include <cuda_fp16.h>
#include <stdint.h>

#define RES    32
#define BATCH  2
#define LTOK   32768
#define CDIM   256
#define HEADS  8
#define HDV    32
#define SWIN   256
// scale * log2(e): exp(s) == 2^(s*log2e), folded into Q pre-scale
#define SCALEE 0.25505654201513125f

#define NT     256
#define HSTR_B 80      // fp16 tile row stride: 40 halves = 80B (ldsm conflict-free)

// byte offsets in smem
#define QS_B   0        // Q fp16 [256][40]; O staging overlays QS+KS
#define KS_B   20480    // K fp16 [256][40]
#define VS_B   40960    // V fp16 [256][40]
#define W_B    61440    // conv w, 288 fp32
#define BI_B   62592    // conv b, 32 fp32
#define SMEM_BYTES 62720
// O staging: fp32 [256][36] overlaid on QS_B.. (spills into KS region ->
// __syncthreads() must separate main-loop K reads from staging writes)
#define OSTR   36

__device__ __forceinline__ float ex2f(float x) {
    float r; asm("ex2.approx.f32 %0, %1;" : "=f"(r) : "f"(x)); return r;
}
__device__ __forceinline__ uint32_t h2u(__half2 h) {
    return *reinterpret_cast<uint32_t*>(&h);
}
__device__ __forceinline__ uint32_t smem_u32(const void* p) {
    uint32_t a;
    asm("{ .reg .u64 t; cvta.to.shared.u64 t, %1; cvt.u32.u64 %0, t; }" : "=r"(a) : "l"(p));
    return a;
}
__device__ __forceinline__ void ldsm4(uint32_t* r, uint32_t addr) {
    asm volatile("ldmatrix.sync.aligned.m8n8.x4.shared.b16 {%0,%1,%2,%3}, [%4];"
        : "=r"(r[0]), "=r"(r[1]), "=r"(r[2]), "=r"(r[3]) : "r"(addr));
}
__device__ __forceinline__ void ldsm4t(uint32_t* r, uint32_t addr) {
    asm volatile("ldmatrix.sync.aligned.m8n8.x4.trans.shared.b16 {%0,%1,%2,%3}, [%4];"
        : "=r"(r[0]), "=r"(r[1]), "=r"(r[2]), "=r"(r[3]) : "r"(addr));
}
__device__ __forceinline__ void sts64(uint32_t addr, uint32_t a, uint32_t b) {
    asm volatile("st.shared.v2.b32 [%0], {%1, %2};" :: "r"(addr), "r"(a), "r"(b) : "memory");
}
// D(f32) += A(f16) * B(f16),  m16n8k16
__device__ __forceinline__ void mma16(float* d, const uint32_t* a, const uint32_t* b) {
    asm("mma.sync.aligned.m16n8k16.row.col.f32.f16.f16.f32 "
        "{%0,%1,%2,%3}, {%4,%5,%6,%7}, {%8,%9}, {%0,%1,%2,%3};"
        : "+f"(d[0]), "+f"(d[1]), "+f"(d[2]), "+f"(d[3])
        : "r"(a[0]), "r"(a[1]), "r"(a[2]), "r"(a[3]), "r"(b[0]), "r"(b[1]));
}

__global__ void __launch_bounds__(NT, 2)
lepe_attn_h16(const float* __restrict__ qkv,
              const float* __restrict__ conv_w,
              const float* __restrict__ conv_b,
              float* __restrict__ out)
{
    extern __shared__ float smem[];
    char* smb = (char*)smem;
    float* Wsm = (float*)(smb + W_B);
    float* Bsm = (float*)(smb + BI_B);
    const uint32_t sb = smem_u32(smem);

    const int tid  = threadIdx.x;
    const int lane = tid & 31;
    const int warp = tid >> 5;
    const int g    = lane >> 2;
    const int tg   = lane & 3;
    const int m0   = warp * 32;

    const int head = blockIdx.x & 7;
    const int wi   = blockIdx.x >> 3;
    const int b    = wi >> 7;
    const int dsl  = (wi >> 2) & 31;
    const int iw   = wi & 3;

    // ---- stage Q/K/V, coalesced: 8 lanes cooperate on one token row ----
    {
        const int piece = lane & 7;           // which float4 of the 32-ch row
        const size_t qkv_k = (size_t)BATCH * LTOK * CDIM;
#pragma unroll
        for (int it = 0; it < 8; it++) {
            const int tok = m0 + it * 4 + (lane >> 3);
            const int l = dsl * 1024 + (tok >> 3) * 32 + iw * 8 + (tok & 7);
            const size_t base = ((size_t)b * LTOK + l) * CDIM + head * HDV + piece * 4;
            const uint32_t sad = (uint32_t)(tok * HSTR_B + piece * 8);
            float4 qq = *(const float4*)(qkv + base);
            *(uint2*)(smb + QS_B + sad) = make_uint2(
                h2u(__floats2half2_rn(qq.x * SCALEE, qq.y * SCALEE)),
                h2u(__floats2half2_rn(qq.z * SCALEE, qq.w * SCALEE)));
            float4 kk = *(const float4*)(qkv + qkv_k + base);
            *(uint2*)(smb + KS_B + sad) = make_uint2(
                h2u(__floats2half2_rn(kk.x, kk.y)),
                h2u(__floats2half2_rn(kk.z, kk.w)));
            float4 vv = *(const float4*)(qkv + 2 * qkv_k + base);
            *(uint2*)(smb + VS_B + sad) = make_uint2(
                h2u(__floats2half2_rn(vv.x, vv.y)),
                h2u(__floats2half2_rn(vv.z, vv.w)));
        }
        for (int i = tid; i < 9 * HDV; i += NT) Wsm[i] = conv_w[head * HDV * 9 + i];
        if (tid < HDV) Bsm[tid] = conv_b[head * HDV + tid];
    }
    __syncthreads();

    const int lane7 = lane & 7;
    const int lb8   = (lane >> 3) & 1;
    const int lb16  = (lane >> 4) & 1;
    // A-pattern (Q): rows (m0 + lane7 + lb8*8), k-col half lb16*16B
    const uint32_t a_base = sb + QS_B + (uint32_t)(m0 + lane7 + lb8 * 8) * HSTR_B + lb16 * 16;
    // B-pattern (K): rows (key lane7 + lb16*8), k-col half lb8*16B
    const uint32_t k_base = sb + KS_B + (uint32_t)(lane7 + lb16 * 8) * HSTR_B + lb8 * 16;
    // B-trans pattern (V): rows (key lane7 + lb8*8), d-col half lb16*16B
    const uint32_t v_base = sb + VS_B + (uint32_t)(lane7 + lb8 * 8) * HSTR_B + lb16 * 16;
    // O staging (fp32, stride 36): row (m0+g), col 2tg
    const uint32_t o_st = sb + QS_B + ((uint32_t)(m0 + g) * OSTR + 2 * tg) * 4;

    // ---- Q fragments: 2 m-tiles x 2 k-steps ----
    uint32_t qf[2][2][4];
#pragma unroll
    for (int mt = 0; mt < 2; mt++)
#pragma unroll
        for (int ks = 0; ks < 2; ks++)
            ldsm4(qf[mt][ks], a_base + mt * (16 * HSTR_B) + ks * 32);

    float o[2][4][4];
    float rs[2][2];
#pragma unroll
    for (int mt = 0; mt < 2; mt++) {
        rs[mt][0] = 0.f; rs[mt][1] = 0.f;
#pragma unroll
        for (int nt = 0; nt < 4; nt++)
#pragma unroll
            for (int i = 0; i < 4; i++) o[mt][nt][i] = 0.f;
    }

    // ---- main loop: 8 chunks of 32 keys, register-local softmax ----
    for (int c0 = 0; c0 < SWIN; c0 += 32) {
        float p[2][4][4];
#pragma unroll
        for (int mt = 0; mt < 2; mt++)
#pragma unroll
            for (int nt = 0; nt < 4; nt++)
#pragma unroll
                for (int i = 0; i < 4; i++) p[mt][nt][i] = 0.f;

        // S = Q K^T
#pragma unroll
        for (int ks = 0; ks < 2; ks++) {
            uint32_t kf0[4], kf1[4];
            ldsm4(kf0, k_base + (uint32_t)(c0 * HSTR_B) + ks * 32);
            ldsm4(kf1, k_base + (uint32_t)((c0 + 16) * HSTR_B) + ks * 32);
#pragma unroll
            for (int mt = 0; mt < 2; mt++) {
                mma16(p[mt][0], qf[mt][ks], kf0);
                mma16(p[mt][1], qf[mt][ks], kf0 + 2);
                mma16(p[mt][2], qf[mt][ks], kf1);
                mma16(p[mt][3], qf[mt][ks], kf1 + 2);
            }
        }

        // p = 2^s; C-frag of S == A-frag of P: pack directly into A-frags
        uint32_t af[2][2][4];
#pragma unroll
        for (int mt = 0; mt < 2; mt++)
#pragma unroll
            for (int nt = 0; nt < 4; nt++) {
                float e0 = ex2f(p[mt][nt][0]);
                float e1 = ex2f(p[mt][nt][1]);
                float e2 = ex2f(p[mt][nt][2]);
                float e3 = ex2f(p[mt][nt][3]);
                rs[mt][0] += e0 + e1;
                rs[mt][1] += e2 + e3;
                af[mt][nt >> 1][(nt & 1) * 2 + 0] = h2u(__floats2half2_rn(e0, e1));
                af[mt][nt >> 1][(nt & 1) * 2 + 1] = h2u(__floats2half2_rn(e2, e3));
            }

        // O += P V
#pragma unroll
        for (int ks = 0; ks < 2; ks++) {
            uint32_t vf0[4], vf1[4];
            ldsm4t(vf0, v_base + (uint32_t)((c0 + ks * 16) * HSTR_B));
            ldsm4t(vf1, v_base + (uint32_t)((c0 + ks * 16) * HSTR_B) + 32);
#pragma unroll
            for (int mt = 0; mt < 2; mt++) {
                mma16(o[mt][0], af[mt][ks], vf0);
                mma16(o[mt][1], af[mt][ks], vf0 + 2);
                mma16(o[mt][2], af[mt][ks], vf1);
                mma16(o[mt][3], af[mt][ks], vf1 + 2);
            }
        }
    }

    // All warps must finish reading K/Q smem before O staging overwrites them.
    __syncthreads();

    // ---- row-sum quad reduce + normalized O -> fp32 staging (over Q+K region) ----
#pragma unroll
    for (int mt = 0; mt < 2; mt++) {
#pragma unroll
        for (int r = 0; r < 2; r++) {
            float s = rs[mt][r];
            s += __shfl_xor_sync(0xffffffffu, s, 1);
            s += __shfl_xor_sync(0xffffffffu, s, 2);
            rs[mt][r] = 1.0f / s;
        }
#pragma unroll
        for (int nt = 0; nt < 4; nt++) {
            uint32_t ad = o_st + (mt * 16 * OSTR + nt * 8) * 4;
            sts64(ad, __float_as_uint(o[mt][nt][0] * rs[mt][0]),
                      __float_as_uint(o[mt][nt][1] * rs[mt][0]));
            sts64(ad + 8 * OSTR * 4, __float_as_uint(o[mt][nt][2] * rs[mt][1]),
                                     __float_as_uint(o[mt][nt][3] * rs[mt][1]));
        }
    }
    __syncthreads();

    // ---- epilogue: conv mapping flip — warp = 2 tokens/iter, lane = d2 chan ----
    {
        const int d2   = lane & 15;           // channel pair index (0..15)
        const int side = lane >> 4;           // which of the 2 tokens
        // preload this lane's conv weights (channels 2*d2, 2*d2+1) and bias
        float w0[9], w1[9];
#pragma unroll
        for (int t = 0; t < 9; t++) {
            w0[t] = Wsm[(2 * d2) * 9 + t];
            w1[t] = Wsm[(2 * d2 + 1) * 9 + t];
        }
        const float b0 = Bsm[2 * d2], b1 = Bsm[2 * d2 + 1];

#pragma unroll
        for (int it = 0; it < 16; it++) {
            const int tok = m0 + it * 2 + side;
            const int h = tok >> 3, w = tok & 7;
            float2 oo = *(const float2*)(smb + QS_B + (tok * OSTR + 2 * d2) * 4);
            float a0 = oo.x + b0;
            float a1 = oo.y + b1;
#pragma unroll
            for (int dh = -1; dh <= 1; dh++) {
                const int hh = h + dh;
                if (hh < 0 || hh >= RES) continue;
#pragma unroll
                for (int dw = -1; dw <= 1; dw++) {
                    const int ww = w + dw;
                    if (ww < 0 || ww >= 8) continue;
                    const int k = hh * 8 + ww;
                    const int t = (dh + 1) * 3 + (dw + 1);
                    float2 fv = __half22float2(
                        *(const __half2*)(smb + VS_B + k * HSTR_B + d2 * 4));
                    a0 += w0[t] * fv.x;
                    a1 += w1[t] * fv.y;
                }
            }
            const int l = dsl * 1024 + h * 32 + iw * 8 + w;
            float* op = out + ((size_t)b * LTOK + l) * CDIM + head * HDV + 2 * d2;
            *(float2*)op = make_float2(a0, a1);
        }
    }
}

extern "C" void kernel_launch(void* const* d_in, const int* in_sizes, int n_in,
                              void* d_out, int out_size)
{
    const float* qkv    = (const float*)d_in[0];
    const float* conv_w = (const float*)d_in[1];
    const float* conv_b = (const float*)d_in[2];
    float* out = (float*)d_out;

    cudaFuncSetAttribute(lepe_attn_h16,
                         cudaFuncAttributeMaxDynamicSharedMemorySize, SMEM_BYTES);
    lepe_attn_h16<<<2048, NT, SMEM_BYTES>>>(qkv, conv_w, conv_b, out);
}

// round 11
// speedup vs baseline: 7.9388x; 1.1138x over previous
#include <cuda_runtime.h>
#include <cuda_fp16.h>
#include <stdint.h>

#define RES    32
#define BATCH  2
#define LTOK   32768
#define CDIM   256
#define HEADS  8
#define HDV    32
#define SWIN   256
// scale * log2(e): exp(s) == 2^(s*log2e), folded into Q pre-scale
#define SCALEE 0.25505654201513125f

#define NT     256
#define HSTR_B 80      // fp16 tile row stride: 40 halves = 80B

// byte offsets in smem
#define QS_B   0        // Q fp16 [256][40]; O staging overlays QS+KS
#define KS_B   20480    // K fp16 [256][40]
#define VS_B   40960    // V fp16 [256][40]
#define W_B    61440    // conv w, 288 fp32
#define BI_B   62592    // conv b, 32 fp32
#define SMEM_BYTES 62720
// O staging: fp32 [256][36] overlaid on QS_B.. (spills into KS region ->
// __syncthreads() must separate main-loop K reads from staging writes)
#define OSTR   36

__device__ __forceinline__ uint32_t h2u(__half2 h) {
    return *reinterpret_cast<uint32_t*>(&h);
}
__device__ __forceinline__ uint32_t smem_u32(const void* p) {
    uint32_t a;
    asm("{ .reg .u64 t; cvta.to.shared.u64 t, %1; cvt.u32.u64 %0, t; }" : "=r"(a) : "l"(p));
    return a;
}
// pack two f32 into f16x2: lo goes to low half
__device__ __forceinline__ uint32_t packh2(float hi, float lo) {
    uint32_t r;
    asm("cvt.rn.f16x2.f32 %0, %1, %2;" : "=r"(r) : "f"(hi), "f"(lo));
    return r;
}
// 2^x on both halves, one MUFU op
__device__ __forceinline__ uint32_t ex2h2(uint32_t x) {
    uint32_t r;
    asm("ex2.approx.f16x2 %0, %1;" : "=r"(r) : "r"(x));
    return r;
}
__device__ __forceinline__ void ldsm4(uint32_t* r, uint32_t addr) {
    asm volatile("ldmatrix.sync.aligned.m8n8.x4.shared.b16 {%0,%1,%2,%3}, [%4];"
        : "=r"(r[0]), "=r"(r[1]), "=r"(r[2]), "=r"(r[3]) : "r"(addr));
}
__device__ __forceinline__ void ldsm4t(uint32_t* r, uint32_t addr) {
    asm volatile("ldmatrix.sync.aligned.m8n8.x4.trans.shared.b16 {%0,%1,%2,%3}, [%4];"
        : "=r"(r[0]), "=r"(r[1]), "=r"(r[2]), "=r"(r[3]) : "r"(addr));
}
__device__ __forceinline__ void sts64(uint32_t addr, uint32_t a, uint32_t b) {
    asm volatile("st.shared.v2.b32 [%0], {%1, %2};" :: "r"(addr), "r"(a), "r"(b) : "memory");
}
// D(f32) += A(f16) * B(f16),  m16n8k16
__device__ __forceinline__ void mma16(float* d, const uint32_t* a, const uint32_t* b) {
    asm("mma.sync.aligned.m16n8k16.row.col.f32.f16.f16.f32 "
        "{%0,%1,%2,%3}, {%4,%5,%6,%7}, {%8,%9}, {%0,%1,%2,%3};"
        : "+f"(d[0]), "+f"(d[1]), "+f"(d[2]), "+f"(d[3])
        : "r"(a[0]), "r"(a[1]), "r"(a[2]), "r"(a[3]), "r"(b[0]), "r"(b[1]));
}

__global__ void __launch_bounds__(NT, 2)
lepe_attn_h16(const float* __restrict__ qkv,
              const float* __restrict__ conv_w,
              const float* __restrict__ conv_b,
              float* __restrict__ out)
{
    extern __shared__ float smem[];
    char* smb = (char*)smem;
    float* Wsm = (float*)(smb + W_B);
    float* Bsm = (float*)(smb + BI_B);
    const uint32_t sb = smem_u32(smem);

    const int tid  = threadIdx.x;
    const int lane = tid & 31;
    const int warp = tid >> 5;
    const int g    = lane >> 2;
    const int tg   = lane & 3;
    const int m0   = warp * 32;

    const int head = blockIdx.x & 7;
    const int wi   = blockIdx.x >> 3;
    const int b    = wi >> 7;
    const int dsl  = (wi >> 2) & 31;
    const int iw   = wi & 3;

    // ---- stage Q/K/V, coalesced: 8 lanes cooperate on one token row ----
    {
        const int piece = lane & 7;
        const size_t qkv_k = (size_t)BATCH * LTOK * CDIM;
#pragma unroll
        for (int it = 0; it < 8; it++) {
            const int tok = m0 + it * 4 + (lane >> 3);
            const int l = dsl * 1024 + (tok >> 3) * 32 + iw * 8 + (tok & 7);
            const size_t base = ((size_t)b * LTOK + l) * CDIM + head * HDV + piece * 4;
            const uint32_t sad = (uint32_t)(tok * HSTR_B + piece * 8);
            float4 qq = *(const float4*)(qkv + base);
            *(uint2*)(smb + QS_B + sad) = make_uint2(
                h2u(__floats2half2_rn(qq.x * SCALEE, qq.y * SCALEE)),
                h2u(__floats2half2_rn(qq.z * SCALEE, qq.w * SCALEE)));
            float4 kk = *(const float4*)(qkv + qkv_k + base);
            *(uint2*)(smb + KS_B + sad) = make_uint2(
                h2u(__floats2half2_rn(kk.x, kk.y)),
                h2u(__floats2half2_rn(kk.z, kk.w)));
            float4 vv = *(const float4*)(qkv + 2 * qkv_k + base);
            *(uint2*)(smb + VS_B + sad) = make_uint2(
                h2u(__floats2half2_rn(vv.x, vv.y)),
                h2u(__floats2half2_rn(vv.z, vv.w)));
        }
        for (int i = tid; i < 9 * HDV; i += NT) Wsm[i] = conv_w[head * HDV * 9 + i];
        if (tid < HDV) Bsm[tid] = conv_b[head * HDV + tid];
    }
    __syncthreads();

    const int lane7 = lane & 7;
    const int lb8   = (lane >> 3) & 1;
    const int lb16  = (lane >> 4) & 1;
    const uint32_t a_base = sb + QS_B + (uint32_t)(m0 + lane7 + lb8 * 8) * HSTR_B + lb16 * 16;
    const uint32_t k_base = sb + KS_B + (uint32_t)(lane7 + lb16 * 8) * HSTR_B + lb8 * 16;
    const uint32_t v_base = sb + VS_B + (uint32_t)(lane7 + lb8 * 8) * HSTR_B + lb16 * 16;
    const uint32_t o_st = sb + QS_B + ((uint32_t)(m0 + g) * OSTR + 2 * tg) * 4;

    // ---- Q fragments: 2 m-tiles x 2 k-steps ----
    uint32_t qf[2][2][4];
#pragma unroll
    for (int mt = 0; mt < 2; mt++)
#pragma unroll
        for (int ks = 0; ks < 2; ks++)
            ldsm4(qf[mt][ks], a_base + mt * (16 * HSTR_B) + ks * 32);

    float o[2][4][4];
    float rsacc[2][4];   // row sums via P x ones MMA: c0=rowsum(g), c2=rowsum(g+8)
    const uint32_t ones2[2] = {0x3C003C00u, 0x3C003C00u};
#pragma unroll
    for (int mt = 0; mt < 2; mt++) {
#pragma unroll
        for (int i = 0; i < 4; i++) rsacc[mt][i] = 0.f;
#pragma unroll
        for (int nt = 0; nt < 4; nt++)
#pragma unroll
            for (int i = 0; i < 4; i++) o[mt][nt][i] = 0.f;
    }

    // ---- main loop: 8 chunks of 32 keys ----
    for (int c0 = 0; c0 < SWIN; c0 += 32) {
        float p[2][4][4];
#pragma unroll
        for (int mt = 0; mt < 2; mt++)
#pragma unroll
            for (int nt = 0; nt < 4; nt++)
#pragma unroll
                for (int i = 0; i < 4; i++) p[mt][nt][i] = 0.f;

        // S = Q K^T
#pragma unroll
        for (int ks = 0; ks < 2; ks++) {
            uint32_t kf0[4], kf1[4];
            ldsm4(kf0, k_base + (uint32_t)(c0 * HSTR_B) + ks * 32);
            ldsm4(kf1, k_base + (uint32_t)((c0 + 16) * HSTR_B) + ks * 32);
#pragma unroll
            for (int mt = 0; mt < 2; mt++) {
                mma16(p[mt][0], qf[mt][ks], kf0);
                mma16(p[mt][1], qf[mt][ks], kf0 + 2);
                mma16(p[mt][2], qf[mt][ks], kf1);
                mma16(p[mt][3], qf[mt][ks], kf1 + 2);
            }
        }

        // P = 2^S in f16x2 (one MUFU per pair), packed straight into A-frags
        uint32_t af[2][2][4];
#pragma unroll
        for (int mt = 0; mt < 2; mt++)
#pragma unroll
            for (int nt = 0; nt < 4; nt++) {
                af[mt][nt >> 1][(nt & 1) * 2 + 0] =
                    ex2h2(packh2(p[mt][nt][1], p[mt][nt][0]));
                af[mt][nt >> 1][(nt & 1) * 2 + 1] =
                    ex2h2(packh2(p[mt][nt][3], p[mt][nt][2]));
            }

        // row sums: P x ones (exact f32 accumulation in tensor core)
#pragma unroll
        for (int mt = 0; mt < 2; mt++) {
            mma16(rsacc[mt], af[mt][0], ones2);
            mma16(rsacc[mt], af[mt][1], ones2);
        }

        // O += P V
#pragma unroll
        for (int ks = 0; ks < 2; ks++) {
            uint32_t vf0[4], vf1[4];
            ldsm4t(vf0, v_base + (uint32_t)((c0 + ks * 16) * HSTR_B));
            ldsm4t(vf1, v_base + (uint32_t)((c0 + ks * 16) * HSTR_B) + 32);
#pragma unroll
            for (int mt = 0; mt < 2; mt++) {
                mma16(o[mt][0], af[mt][ks], vf0);
                mma16(o[mt][1], af[mt][ks], vf0 + 2);
                mma16(o[mt][2], af[mt][ks], vf1);
                mma16(o[mt][3], af[mt][ks], vf1 + 2);
            }
        }
    }

    // All warps must finish reading K/Q smem before O staging overwrites them.
    __syncthreads();

    // ---- normalize (row sums already complete per lane) + staging ----
#pragma unroll
    for (int mt = 0; mt < 2; mt++) {
        const float inv0 = 1.0f / rsacc[mt][0];   // rowsum(g)
        const float inv1 = 1.0f / rsacc[mt][2];   // rowsum(g+8)
#pragma unroll
        for (int nt = 0; nt < 4; nt++) {
            uint32_t ad = o_st + (mt * 16 * OSTR + nt * 8) * 4;
            sts64(ad, __float_as_uint(o[mt][nt][0] * inv0),
                      __float_as_uint(o[mt][nt][1] * inv0));
            sts64(ad + 8 * OSTR * 4, __float_as_uint(o[mt][nt][2] * inv1),
                                     __float_as_uint(o[mt][nt][3] * inv1));
        }
    }
    __syncthreads();

    // ---- epilogue: conv — warp = 2 tokens/iter, lane = d2 channel pair ----
    {
        const int d2   = lane & 15;
        const int side = lane >> 4;
        float w0[9], w1[9];
#pragma unroll
        for (int t = 0; t < 9; t++) {
            w0[t] = Wsm[(2 * d2) * 9 + t];
            w1[t] = Wsm[(2 * d2 + 1) * 9 + t];
        }
        const float b0 = Bsm[2 * d2], b1 = Bsm[2 * d2 + 1];

#pragma unroll
        for (int it = 0; it < 16; it++) {
            const int tok = m0 + it * 2 + side;
            const int h = tok >> 3, w = tok & 7;
            float2 oo = *(const float2*)(smb + QS_B + (tok * OSTR + 2 * d2) * 4);
            float a0 = oo.x + b0;
            float a1 = oo.y + b1;
#pragma unroll
            for (int dh = -1; dh <= 1; dh++) {
                const int hh = h + dh;
                if (hh < 0 || hh >= RES) continue;
#pragma unroll
                for (int dw = -1; dw <= 1; dw++) {
                    const int ww = w + dw;
                    if (ww < 0 || ww >= 8) continue;
                    const int k = hh * 8 + ww;
                    const int t = (dh + 1) * 3 + (dw + 1);
                    float2 fv = __half22float2(
                        *(const __half2*)(smb + VS_B + k * HSTR_B + d2 * 4));
                    a0 += w0[t] * fv.x;
                    a1 += w1[t] * fv.y;
                }
            }
            const int l = dsl * 1024 + h * 32 + iw * 8 + w;
            float* op = out + ((size_t)b * LTOK + l) * CDIM + head * HDV + 2 * d2;
            *(float2*)op = make_float2(a0, a1);
        }
    }
}

extern "C" void kernel_launch(void* const* d_in, const int* in_sizes, int n_in,
                              void* d_out, int out_size)
{
    const float* qkv    = (const float*)d_in[0];
    const float* conv_w = (const float*)d_in[1];
    const float* conv_b = (const float*)d_in[2];
    float* out = (float*)d_out;

    cudaFuncSetAttribute(lepe_attn_h16,
                         cudaFuncAttributeMaxDynamicSharedMemorySize, SMEM_BYTES);
    lepe_attn_h16<<<2048, NT, SMEM_BYTES>>>(qkv, conv_w, conv_b, out);
}